// round 1
// baseline (speedup 1.0000x reference)
#include <cuda_runtime.h>
#include <cuda_bf16.h>
#include <math.h>

#define NMAX 100000
#define EMAX 1600000
#define PMAX 100000
#define DDIM 128

// ---------------- scratch (static __device__ arrays; no allocation) ----------
__device__ float g_h [NMAX * DDIM];   // per-layer transformed features
__device__ float g_x2[NMAX * DDIM];   // after layer 1
__device__ float g_x3[NMAX * DDIM];   // after layer 2 (= z)
__device__ float g_u [NMAX * DDIM];   // z @ lp_w1[:128]
__device__ float g_v [NMAX * DDIM];   // z @ lp_w1[128:]
__device__ float4 g_asrc[NMAX];
__device__ float4 g_adst[NMAX];
__device__ int g_deg   [NMAX];
__device__ int g_rowptr[NMAX + 1];
__device__ int g_cursor[NMAX];
__device__ int g_col   [EMAX];
__device__ int g_bsums [1024];

// ---------------- CSR build ----------------
__global__ void k_zero_deg(int n) {
    int i = blockIdx.x * blockDim.x + threadIdx.x;
    if (i < n) g_deg[i] = 0;
}

__global__ void k_hist(const int* __restrict__ dst, int e) {
    int i = blockIdx.x * blockDim.x + threadIdx.x;
    if (i < e) atomicAdd(&g_deg[dst[i]], 1);
}

__global__ void k_scan1(int n) {
    __shared__ int sm[1024];
    int tid = threadIdx.x;
    int i = blockIdx.x * 1024 + tid;
    int v = (i < n) ? g_deg[i] : 0;
    sm[tid] = v;
    __syncthreads();
    for (int off = 1; off < 1024; off <<= 1) {
        int t = (tid >= off) ? sm[tid - off] : 0;
        __syncthreads();
        sm[tid] += t;
        __syncthreads();
    }
    if (i < n) g_rowptr[i] = sm[tid] - v;   // exclusive
    if (tid == 1023) g_bsums[blockIdx.x] = sm[1023];
}

__global__ void k_scan2(int nb) {
    __shared__ int sm[1024];
    int tid = threadIdx.x;
    int v = (tid < nb) ? g_bsums[tid] : 0;
    sm[tid] = v;
    __syncthreads();
    for (int off = 1; off < 1024; off <<= 1) {
        int t = (tid >= off) ? sm[tid - off] : 0;
        __syncthreads();
        sm[tid] += t;
        __syncthreads();
    }
    if (tid < nb) g_bsums[tid] = sm[tid] - v;  // exclusive
}

__global__ void k_scan3(int n, int e) {
    int i = blockIdx.x * 1024 + threadIdx.x;
    if (i < n) g_rowptr[i] += g_bsums[blockIdx.x];
    if (i == 0) g_rowptr[n] = e;
}

__global__ void k_cursor(int n) {
    int i = blockIdx.x * blockDim.x + threadIdx.x;
    if (i < n) g_cursor[i] = g_rowptr[i];
}

__global__ void k_scatter(const int* __restrict__ src, const int* __restrict__ dst, int e) {
    int i = blockIdx.x * blockDim.x + threadIdx.x;
    if (i < e) {
        int d = dst[i];
        int slot = atomicAdd(&g_cursor[d], 1);
        g_col[slot] = src[i];
    }
}

// ---------------- GEMM: C[n,128] = A[n,128] @ W[128,128] ----------------
__global__ __launch_bounds__(256) void k_gemm128(
    const float* __restrict__ A, const float* __restrict__ W,
    float* __restrict__ C, int n)
{
    __shared__ float As[64][32];
    __shared__ float Ws[32][128];
    int tx = threadIdx.x & 31;
    int ty = threadIdx.x >> 5;
    int row0 = blockIdx.x * 64;

    float acc[8][4];
#pragma unroll
    for (int i = 0; i < 8; i++)
#pragma unroll
        for (int j = 0; j < 4; j++) acc[i][j] = 0.f;

    for (int k0 = 0; k0 < 128; k0 += 32) {
        __syncthreads();
        for (int j = threadIdx.x; j < 64 * 32; j += 256) {
            int r = j >> 5, k = j & 31;
            int gr = row0 + r;
            As[r][k] = (gr < n) ? A[(size_t)gr * 128 + k0 + k] : 0.f;
        }
        for (int j = threadIdx.x; j < 32 * 128; j += 256) {
            int r = j >> 7, c = j & 127;
            Ws[r][c] = W[(size_t)(k0 + r) * 128 + c];
        }
        __syncthreads();
#pragma unroll
        for (int k = 0; k < 32; k++) {
            float4 w = *reinterpret_cast<const float4*>(&Ws[k][tx * 4]);
#pragma unroll
            for (int i = 0; i < 8; i++) {
                float a = As[ty + 8 * i][k];
                acc[i][0] += a * w.x;
                acc[i][1] += a * w.y;
                acc[i][2] += a * w.z;
                acc[i][3] += a * w.w;
            }
        }
    }
#pragma unroll
    for (int i = 0; i < 8; i++) {
        int gr = row0 + ty + 8 * i;
        if (gr < n) {
            float4 o = make_float4(acc[i][0], acc[i][1], acc[i][2], acc[i][3]);
            *reinterpret_cast<float4*>(&C[(size_t)gr * 128 + tx * 4]) = o;
        }
    }
}

// ---------------- per-node alpha: asrc[n][h] = sum_dh h[n,h,dh]*a_src[h,dh] --
__device__ __forceinline__ float warp_sum(float v) {
#pragma unroll
    for (int o = 16; o; o >>= 1) v += __shfl_xor_sync(0xffffffffu, v, o);
    return v;
}
__device__ __forceinline__ float warp_max(float v) {
#pragma unroll
    for (int o = 16; o; o >>= 1) v = fmaxf(v, __shfl_xor_sync(0xffffffffu, v, o));
    return v;
}

__global__ void k_alpha(const float* __restrict__ h,
                        const float* __restrict__ a_src,
                        const float* __restrict__ a_dst, int n)
{
    int gw = (blockIdx.x * blockDim.x + threadIdx.x) >> 5;
    int lane = threadIdx.x & 31;
    if (gw >= n) return;
    const float* hr = h + (size_t)gw * 128;
    float ps[4], pd[4];
#pragma unroll
    for (int hh = 0; hh < 4; hh++) {
        float hv = hr[hh * 32 + lane];
        ps[hh] = hv * a_src[hh * 32 + lane];
        pd[hh] = hv * a_dst[hh * 32 + lane];
    }
#pragma unroll
    for (int hh = 0; hh < 4; hh++) { ps[hh] = warp_sum(ps[hh]); pd[hh] = warp_sum(pd[hh]); }
    if (lane == 0) {
        g_asrc[gw] = make_float4(ps[0], ps[1], ps[2], ps[3]);
        g_adst[gw] = make_float4(pd[0], pd[1], pd[2], pd[3]);
    }
}

// ---------------- fused GAT aggregation + ELU + residual --------------------
__device__ __forceinline__ float lrelu(float x) { return x >= 0.f ? x : 0.2f * x; }
__device__ __forceinline__ float elu(float x)  { return x > 0.f ? x : expm1f(x); }

__global__ void k_edgeagg(const float* __restrict__ h,
                          const float* __restrict__ xprev,
                          float* __restrict__ xnext, int n)
{
    int gw = (blockIdx.x * blockDim.x + threadIdx.x) >> 5;
    int lane = threadIdx.x & 31;
    if (gw >= n) return;

    int base = g_rowptr[gw];
    int deg  = g_rowptr[gw + 1] - base;
    float4 ad = g_adst[gw];

    // pass 1: per-head max, clamped at 0
    float m0 = -INFINITY, m1 = -INFINITY, m2 = -INFINITY, m3 = -INFINITY;
    for (int i = lane; i < deg; i += 32) {
        int s = g_col[base + i];
        float4 as = g_asrc[s];
        m0 = fmaxf(m0, lrelu(as.x + ad.x));
        m1 = fmaxf(m1, lrelu(as.y + ad.y));
        m2 = fmaxf(m2, lrelu(as.z + ad.z));
        m3 = fmaxf(m3, lrelu(as.w + ad.w));
    }
    m0 = fmaxf(warp_max(m0), 0.f);
    m1 = fmaxf(warp_max(m1), 0.f);
    m2 = fmaxf(warp_max(m2), 0.f);
    m3 = fmaxf(warp_max(m3), 0.f);

    // pass 2: per-head sum of exp
    float s0 = 0.f, s1 = 0.f, s2 = 0.f, s3 = 0.f;
    for (int i = lane; i < deg; i += 32) {
        int s = g_col[base + i];
        float4 as = g_asrc[s];
        s0 += expf(lrelu(as.x + ad.x) - m0);
        s1 += expf(lrelu(as.y + ad.y) - m1);
        s2 += expf(lrelu(as.z + ad.z) - m2);
        s3 += expf(lrelu(as.w + ad.w) - m3);
    }
    s0 = warp_sum(s0); s1 = warp_sum(s1); s2 = warp_sum(s2); s3 = warp_sum(s3);
    float i0 = 1.f / (s0 + 1e-10f);
    float i1 = 1.f / (s1 + 1e-10f);
    float i2 = 1.f / (s2 + 1e-10f);
    float i3 = 1.f / (s3 + 1e-10f);

    // pass 3: weighted aggregation (lane owns dh = lane, all 4 heads)
    float a0 = 0.f, a1 = 0.f, a2 = 0.f, a3 = 0.f;
    for (int base_i = 0; base_i < deg; base_i += 32) {
        int cnt = min(32, deg - base_i);
        int mys = 0;
        float w0 = 0.f, w1 = 0.f, w2 = 0.f, w3 = 0.f;
        if (lane < cnt) {
            mys = g_col[base + base_i + lane];
            float4 as = g_asrc[mys];
            w0 = expf(lrelu(as.x + ad.x) - m0) * i0;
            w1 = expf(lrelu(as.y + ad.y) - m1) * i1;
            w2 = expf(lrelu(as.z + ad.z) - m2) * i2;
            w3 = expf(lrelu(as.w + ad.w) - m3) * i3;
        }
        for (int j = 0; j < cnt; j++) {
            int s   = __shfl_sync(0xffffffffu, mys, j);
            float c0 = __shfl_sync(0xffffffffu, w0, j);
            float c1 = __shfl_sync(0xffffffffu, w1, j);
            float c2 = __shfl_sync(0xffffffffu, w2, j);
            float c3 = __shfl_sync(0xffffffffu, w3, j);
            const float* hr = h + (size_t)s * 128;
            a0 += hr[lane]      * c0;
            a1 += hr[32 + lane] * c1;
            a2 += hr[64 + lane] * c2;
            a3 += hr[96 + lane] * c3;
        }
    }

    size_t o = (size_t)gw * 128 + lane;
    xnext[o]      = elu(a0) + xprev[o];
    xnext[o + 32] = elu(a1) + xprev[o + 32];
    xnext[o + 64] = elu(a2) + xprev[o + 64];
    xnext[o + 96] = elu(a3) + xprev[o + 96];
}

// ---------------- pair epilogue: logits = relu(u[s]+v[d]+b1) @ w2 + b2 ------
__global__ void k_pairs(const int* __restrict__ lsrc, const int* __restrict__ ldst,
                        const float* __restrict__ b1, const float* __restrict__ w2,
                        const float* __restrict__ b2, float* __restrict__ out, int p)
{
    int gw = (blockIdx.x * blockDim.x + threadIdx.x) >> 5;
    int lane = threadIdx.x & 31;
    if (gw >= p) return;
    const float* up = g_u + (size_t)lsrc[gw] * 128;
    const float* vp = g_v + (size_t)ldst[gw] * 128;
    float t = 0.f;
#pragma unroll
    for (int hh = 0; hh < 4; hh++) {
        int k = hh * 32 + lane;
        float hid = up[k] + vp[k] + b1[k];
        hid = fmaxf(hid, 0.f);
        t += hid * w2[k];
    }
    t = warp_sum(t);
    if (lane == 0) out[gw] = t + b2[0];
}

// ---------------- driver ----------------
extern "C" void kernel_launch(void* const* d_in, const int* in_sizes, int n_in,
                              void* d_out, int out_size)
{
    const float* embed  = (const float*)d_in[0];
    const float* W1     = (const float*)d_in[1];
    const float* a_src1 = (const float*)d_in[2];
    const float* a_dst1 = (const float*)d_in[3];
    const float* W2     = (const float*)d_in[4];
    const float* a_src2 = (const float*)d_in[5];
    const float* a_dst2 = (const float*)d_in[6];
    const float* lp_w1  = (const float*)d_in[7];
    const float* lp_b1  = (const float*)d_in[8];
    const float* lp_w2  = (const float*)d_in[9];
    const float* lp_b2  = (const float*)d_in[10];
    const int*   eidx   = (const int*)d_in[11];
    const int*   lsrc   = (const int*)d_in[12];
    const int*   ldst   = (const int*)d_in[13];
    float* out = (float*)d_out;

    const int N = in_sizes[0] / DDIM;
    const int E = in_sizes[11] / 2;
    const int P = in_sizes[12];
    const int* esrc = eidx;
    const int* edst = eidx + E;

    float* hbuf; cudaGetSymbolAddress((void**)&hbuf, g_h);
    float* x2;   cudaGetSymbolAddress((void**)&x2,   g_x2);
    float* x3;   cudaGetSymbolAddress((void**)&x3,   g_x3);
    float* ub;   cudaGetSymbolAddress((void**)&ub,   g_u);
    float* vb;   cudaGetSymbolAddress((void**)&vb,   g_v);

    const int T = 256;
    int nbN   = (N + T - 1) / T;
    int nbE   = (E + T - 1) / T;
    int nbS   = (N + 1023) / 1024;
    int nbW   = (N * 32 + T - 1) / T;   // warp-per-node kernels
    int nbPW  = (P * 32 + T - 1) / T;
    int nbG   = (N + 63) / 64;

    // CSR by dst (shared by both layers)
    k_zero_deg<<<nbN, T>>>(N);
    k_hist<<<nbE, T>>>(edst, E);
    k_scan1<<<nbS, 1024>>>(N);
    k_scan2<<<1, 1024>>>(nbS);
    k_scan3<<<nbS, 1024>>>(N, E);
    k_cursor<<<nbN, T>>>(N);
    k_scatter<<<nbE, T>>>(esrc, edst, E);

    // layer 1
    k_gemm128<<<nbG, T>>>(embed, W1, hbuf, N);
    k_alpha<<<nbW, T>>>(hbuf, a_src1, a_dst1, N);
    k_edgeagg<<<nbW, T>>>(hbuf, embed, x2, N);

    // layer 2
    k_gemm128<<<nbG, T>>>(x2, W2, hbuf, N);
    k_alpha<<<nbW, T>>>(hbuf, a_src2, a_dst2, N);
    k_edgeagg<<<nbW, T>>>(hbuf, x2, x3, N);

    // link predictor: u = z @ lp_w1[:128], v = z @ lp_w1[128:]
    k_gemm128<<<nbG, T>>>(x3, lp_w1, ub, N);
    k_gemm128<<<nbG, T>>>(x3, lp_w1 + 128 * 128, vb, N);
    k_pairs<<<nbPW, T>>>(lsrc, ldst, lp_b1, lp_w2, lp_b2, out, P);
}

// round 2
// speedup vs baseline: 1.4573x; 1.4573x over previous
#include <cuda_runtime.h>
#include <cuda_bf16.h>
#include <math.h>

#define NMAX 100000
#define EMAX 1600000
#define PMAX 100000
#define DDIM 128

// ---------------- scratch (static __device__ arrays; no allocation) ----------
__device__ float g_h [NMAX * DDIM];   // per-layer transformed features
__device__ float g_x2[NMAX * DDIM];   // after layer 1
__device__ float g_x3[NMAX * DDIM];   // after layer 2 (= z)
__device__ float g_u [NMAX * DDIM];   // z @ lp_w1[:128]
__device__ float g_v [NMAX * DDIM];   // z @ lp_w1[128:]
__device__ float4 g_asrc[NMAX];
__device__ float4 g_adst[NMAX];
__device__ int g_deg   [NMAX];
__device__ int g_rowptr[NMAX + 1];
__device__ int g_cursor[NMAX];
__device__ int g_col   [EMAX];
__device__ int g_bsums [1024];

// ---------------- CSR build ----------------
__global__ void k_zero_deg(int n) {
    int i = blockIdx.x * blockDim.x + threadIdx.x;
    if (i < n) g_deg[i] = 0;
}

__global__ void k_hist(const int* __restrict__ dst, int e) {
    int i = blockIdx.x * blockDim.x + threadIdx.x;
    if (i < e) atomicAdd(&g_deg[dst[i]], 1);
}

__global__ void k_scan1(int n) {
    __shared__ int sm[1024];
    int tid = threadIdx.x;
    int i = blockIdx.x * 1024 + tid;
    int v = (i < n) ? g_deg[i] : 0;
    sm[tid] = v;
    __syncthreads();
    for (int off = 1; off < 1024; off <<= 1) {
        int t = (tid >= off) ? sm[tid - off] : 0;
        __syncthreads();
        sm[tid] += t;
        __syncthreads();
    }
    if (i < n) g_rowptr[i] = sm[tid] - v;   // exclusive
    if (tid == 1023) g_bsums[blockIdx.x] = sm[1023];
}

__global__ void k_scan2(int nb) {
    __shared__ int sm[1024];
    int tid = threadIdx.x;
    int v = (tid < nb) ? g_bsums[tid] : 0;
    sm[tid] = v;
    __syncthreads();
    for (int off = 1; off < 1024; off <<= 1) {
        int t = (tid >= off) ? sm[tid - off] : 0;
        __syncthreads();
        sm[tid] += t;
        __syncthreads();
    }
    if (tid < nb) g_bsums[tid] = sm[tid] - v;  // exclusive
}

__global__ void k_scan3(int n, int e) {
    int i = blockIdx.x * 1024 + threadIdx.x;
    if (i < n) g_rowptr[i] += g_bsums[blockIdx.x];
    if (i == 0) g_rowptr[n] = e;
}

__global__ void k_cursor(int n) {
    int i = blockIdx.x * blockDim.x + threadIdx.x;
    if (i < n) g_cursor[i] = g_rowptr[i];
}

__global__ void k_scatter(const int* __restrict__ src, const int* __restrict__ dst, int e) {
    int i = blockIdx.x * blockDim.x + threadIdx.x;
    if (i < e) {
        int d = dst[i];
        int slot = atomicAdd(&g_cursor[d], 1);
        g_col[slot] = src[i];
    }
}

// ---------------- GEMM: C[n,128] = A[n,128] @ W[128,128] ----------------
// Tile: 128 rows x 64 cols, 256 threads, 32 acc/thread (8 rows x 4 cols).
// W tile (128x64) resident for full K; A streamed in K=32 chunks.
// A tile uses a 16B-group XOR swizzle so the two broadcast groups per LDS
// (rows r and r+4 across the warp halves) hit different banks.
__global__ __launch_bounds__(256, 3) void k_gemm128(
    const float* __restrict__ A, const float* __restrict__ W,
    float* __restrict__ C, int n)
{
    __shared__ float Ws[128 * 64];   // Ws[k][c], 32 KB
    __shared__ float As[128 * 32];   // swizzled A[r][k-chunk], 16 KB

    int tid = threadIdx.x;
    int tr = tid >> 4;    // 0..15 -> rows tr*4 + {0..3} and +64
    int tc = tid & 15;    // 0..15 -> cols tc*4 + {0..3}
    int row0 = blockIdx.x * 128;
    int col0 = blockIdx.y * 64;

    // Load W[0:128][col0:col0+64] once (2048 float4 / 256 threads = 8 each)
    for (int i = tid; i < 128 * 16; i += 256) {
        int k = i >> 4, cq = i & 15;
        *reinterpret_cast<float4*>(&Ws[k * 64 + cq * 4]) =
            *reinterpret_cast<const float4*>(&W[(size_t)k * 128 + col0 + cq * 4]);
    }

    // per-thread row bases + swizzle keys
    int rbase[8], rsw[8];
#pragma unroll
    for (int i = 0; i < 8; i++) {
        int r = tr * 4 + (i & 3) + (i >> 2) * 64;
        rbase[i] = r * 32;
        rsw[i]   = ((r >> 2) & 7) << 2;
    }

    float acc[8][4];
#pragma unroll
    for (int i = 0; i < 8; i++)
#pragma unroll
        for (int j = 0; j < 4; j++) acc[i][j] = 0.f;

    for (int k0 = 0; k0 < 128; k0 += 32) {
        __syncthreads();
        // Fill As: 128 rows x 32 k = 1024 float4 / 256 threads = 4 each
        for (int i = tid; i < 128 * 8; i += 256) {
            int r = i >> 3, kq = i & 7;
            int gr = row0 + r;
            float4 v = make_float4(0.f, 0.f, 0.f, 0.f);
            if (gr < n)
                v = *reinterpret_cast<const float4*>(&A[(size_t)gr * 128 + k0 + kq * 4]);
            int sw = (kq ^ ((r >> 2) & 7)) << 2;
            *reinterpret_cast<float4*>(&As[r * 32 + sw]) = v;
        }
        __syncthreads();

#pragma unroll
        for (int k = 0; k < 32; k++) {
            float4 w = *reinterpret_cast<const float4*>(&Ws[(k0 + k) * 64 + tc * 4]);
            int kq4 = k & 28;       // (k>>2)<<2
            int klo = k & 3;
            float a[8];
#pragma unroll
            for (int i = 0; i < 8; i++)
                a[i] = As[rbase[i] + (kq4 ^ rsw[i]) + klo];
#pragma unroll
            for (int i = 0; i < 8; i++) {
                acc[i][0] += a[i] * w.x;
                acc[i][1] += a[i] * w.y;
                acc[i][2] += a[i] * w.z;
                acc[i][3] += a[i] * w.w;
            }
        }
    }

#pragma unroll
    for (int i = 0; i < 8; i++) {
        int r = tr * 4 + (i & 3) + (i >> 2) * 64;
        int gr = row0 + r;
        if (gr < n)
            *reinterpret_cast<float4*>(&C[(size_t)gr * 128 + col0 + tc * 4]) =
                make_float4(acc[i][0], acc[i][1], acc[i][2], acc[i][3]);
    }
}

// ---------------- per-node alpha ----------------
__device__ __forceinline__ float warp_sum(float v) {
#pragma unroll
    for (int o = 16; o; o >>= 1) v += __shfl_xor_sync(0xffffffffu, v, o);
    return v;
}
__device__ __forceinline__ float warp_max(float v) {
#pragma unroll
    for (int o = 16; o; o >>= 1) v = fmaxf(v, __shfl_xor_sync(0xffffffffu, v, o));
    return v;
}

__global__ void k_alpha(const float* __restrict__ h,
                        const float* __restrict__ a_src,
                        const float* __restrict__ a_dst, int n)
{
    int gw = (blockIdx.x * blockDim.x + threadIdx.x) >> 5;
    int lane = threadIdx.x & 31;
    if (gw >= n) return;
    const float* hr = h + (size_t)gw * 128;
    float ps[4], pd[4];
#pragma unroll
    for (int hh = 0; hh < 4; hh++) {
        float hv = hr[hh * 32 + lane];
        ps[hh] = hv * a_src[hh * 32 + lane];
        pd[hh] = hv * a_dst[hh * 32 + lane];
    }
#pragma unroll
    for (int hh = 0; hh < 4; hh++) { ps[hh] = warp_sum(ps[hh]); pd[hh] = warp_sum(pd[hh]); }
    if (lane == 0) {
        g_asrc[gw] = make_float4(ps[0], ps[1], ps[2], ps[3]);
        g_adst[gw] = make_float4(pd[0], pd[1], pd[2], pd[3]);
    }
}

// ---------------- fused GAT aggregation + ELU + residual --------------------
__device__ __forceinline__ float lrelu(float x) { return x >= 0.f ? x : 0.2f * x; }
__device__ __forceinline__ float elu(float x)  { return x > 0.f ? x : expm1f(x); }

__global__ void k_edgeagg(const float* __restrict__ h,
                          const float* __restrict__ xprev,
                          float* __restrict__ xnext, int n)
{
    int gw = (blockIdx.x * blockDim.x + threadIdx.x) >> 5;
    int lane = threadIdx.x & 31;
    if (gw >= n) return;

    int base = g_rowptr[gw];
    int deg  = g_rowptr[gw + 1] - base;
    float4 ad = g_adst[gw];

    // pass 1: per-head max, clamped at 0
    float m0 = -INFINITY, m1 = -INFINITY, m2 = -INFINITY, m3 = -INFINITY;
    for (int i = lane; i < deg; i += 32) {
        int s = g_col[base + i];
        float4 as = g_asrc[s];
        m0 = fmaxf(m0, lrelu(as.x + ad.x));
        m1 = fmaxf(m1, lrelu(as.y + ad.y));
        m2 = fmaxf(m2, lrelu(as.z + ad.z));
        m3 = fmaxf(m3, lrelu(as.w + ad.w));
    }
    m0 = fmaxf(warp_max(m0), 0.f);
    m1 = fmaxf(warp_max(m1), 0.f);
    m2 = fmaxf(warp_max(m2), 0.f);
    m3 = fmaxf(warp_max(m3), 0.f);

    // pass 2: per-head sum of exp
    float s0 = 0.f, s1 = 0.f, s2 = 0.f, s3 = 0.f;
    for (int i = lane; i < deg; i += 32) {
        int s = g_col[base + i];
        float4 as = g_asrc[s];
        s0 += expf(lrelu(as.x + ad.x) - m0);
        s1 += expf(lrelu(as.y + ad.y) - m1);
        s2 += expf(lrelu(as.z + ad.z) - m2);
        s3 += expf(lrelu(as.w + ad.w) - m3);
    }
    s0 = warp_sum(s0); s1 = warp_sum(s1); s2 = warp_sum(s2); s3 = warp_sum(s3);
    float i0 = 1.f / (s0 + 1e-10f);
    float i1 = 1.f / (s1 + 1e-10f);
    float i2 = 1.f / (s2 + 1e-10f);
    float i3 = 1.f / (s3 + 1e-10f);

    // pass 3: weighted aggregation (lane owns dh = lane, all 4 heads)
    float a0 = 0.f, a1 = 0.f, a2 = 0.f, a3 = 0.f;
    for (int base_i = 0; base_i < deg; base_i += 32) {
        int cnt = min(32, deg - base_i);
        int mys = 0;
        float w0 = 0.f, w1 = 0.f, w2 = 0.f, w3 = 0.f;
        if (lane < cnt) {
            mys = g_col[base + base_i + lane];
            float4 as = g_asrc[mys];
            w0 = expf(lrelu(as.x + ad.x) - m0) * i0;
            w1 = expf(lrelu(as.y + ad.y) - m1) * i1;
            w2 = expf(lrelu(as.z + ad.z) - m2) * i2;
            w3 = expf(lrelu(as.w + ad.w) - m3) * i3;
        }
        for (int j = 0; j < cnt; j++) {
            int s   = __shfl_sync(0xffffffffu, mys, j);
            float c0 = __shfl_sync(0xffffffffu, w0, j);
            float c1 = __shfl_sync(0xffffffffu, w1, j);
            float c2 = __shfl_sync(0xffffffffu, w2, j);
            float c3 = __shfl_sync(0xffffffffu, w3, j);
            const float* hr = h + (size_t)s * 128;
            a0 += hr[lane]      * c0;
            a1 += hr[32 + lane] * c1;
            a2 += hr[64 + lane] * c2;
            a3 += hr[96 + lane] * c3;
        }
    }

    size_t o = (size_t)gw * 128 + lane;
    xnext[o]      = elu(a0) + xprev[o];
    xnext[o + 32] = elu(a1) + xprev[o + 32];
    xnext[o + 64] = elu(a2) + xprev[o + 64];
    xnext[o + 96] = elu(a3) + xprev[o + 96];
}

// ---------------- pair epilogue: logits = relu(u[s]+v[d]+b1) @ w2 + b2 ------
__global__ void k_pairs(const int* __restrict__ lsrc, const int* __restrict__ ldst,
                        const float* __restrict__ b1, const float* __restrict__ w2,
                        const float* __restrict__ b2, float* __restrict__ out, int p)
{
    int gw = (blockIdx.x * blockDim.x + threadIdx.x) >> 5;
    int lane = threadIdx.x & 31;
    if (gw >= p) return;
    const float* up = g_u + (size_t)lsrc[gw] * 128;
    const float* vp = g_v + (size_t)ldst[gw] * 128;
    float t = 0.f;
#pragma unroll
    for (int hh = 0; hh < 4; hh++) {
        int k = hh * 32 + lane;
        float hid = up[k] + vp[k] + b1[k];
        hid = fmaxf(hid, 0.f);
        t += hid * w2[k];
    }
    t = warp_sum(t);
    if (lane == 0) out[gw] = t + b2[0];
}

// ---------------- driver ----------------
extern "C" void kernel_launch(void* const* d_in, const int* in_sizes, int n_in,
                              void* d_out, int out_size)
{
    const float* embed  = (const float*)d_in[0];
    const float* W1     = (const float*)d_in[1];
    const float* a_src1 = (const float*)d_in[2];
    const float* a_dst1 = (const float*)d_in[3];
    const float* W2     = (const float*)d_in[4];
    const float* a_src2 = (const float*)d_in[5];
    const float* a_dst2 = (const float*)d_in[6];
    const float* lp_w1  = (const float*)d_in[7];
    const float* lp_b1  = (const float*)d_in[8];
    const float* lp_w2  = (const float*)d_in[9];
    const float* lp_b2  = (const float*)d_in[10];
    const int*   eidx   = (const int*)d_in[11];
    const int*   lsrc   = (const int*)d_in[12];
    const int*   ldst   = (const int*)d_in[13];
    float* out = (float*)d_out;

    const int N = in_sizes[0] / DDIM;
    const int E = in_sizes[11] / 2;
    const int P = in_sizes[12];
    const int* esrc = eidx;
    const int* edst = eidx + E;

    float* hbuf; cudaGetSymbolAddress((void**)&hbuf, g_h);
    float* x2;   cudaGetSymbolAddress((void**)&x2,   g_x2);
    float* x3;   cudaGetSymbolAddress((void**)&x3,   g_x3);
    float* ub;   cudaGetSymbolAddress((void**)&ub,   g_u);
    float* vb;   cudaGetSymbolAddress((void**)&vb,   g_v);

    const int T = 256;
    int nbN   = (N + T - 1) / T;
    int nbE   = (E + T - 1) / T;
    int nbS   = (N + 1023) / 1024;
    int nbW   = (N * 32 + T - 1) / T;   // warp-per-node kernels
    int nbPW  = (P * 32 + T - 1) / T;

    dim3 gemmGrid((N + 127) / 128, 2);

    // CSR by dst (shared by both layers)
    k_zero_deg<<<nbN, T>>>(N);
    k_hist<<<nbE, T>>>(edst, E);
    k_scan1<<<nbS, 1024>>>(N);
    k_scan2<<<1, 1024>>>(nbS);
    k_scan3<<<nbS, 1024>>>(N, E);
    k_cursor<<<nbN, T>>>(N);
    k_scatter<<<nbE, T>>>(esrc, edst, E);

    // layer 1
    k_gemm128<<<gemmGrid, T>>>(embed, W1, hbuf, N);
    k_alpha<<<nbW, T>>>(hbuf, a_src1, a_dst1, N);
    k_edgeagg<<<nbW, T>>>(hbuf, embed, x2, N);

    // layer 2
    k_gemm128<<<gemmGrid, T>>>(x2, W2, hbuf, N);
    k_alpha<<<nbW, T>>>(hbuf, a_src2, a_dst2, N);
    k_edgeagg<<<nbW, T>>>(hbuf, x2, x3, N);

    // link predictor: u = z @ lp_w1[:128], v = z @ lp_w1[128:]
    k_gemm128<<<gemmGrid, T>>>(x3, lp_w1, ub, N);
    k_gemm128<<<gemmGrid, T>>>(x3, lp_w1 + 128 * 128, vb, N);
    k_pairs<<<nbPW, T>>>(lsrc, ldst, lp_b1, lp_w2, lp_b2, out, P);
}

// round 4
// speedup vs baseline: 1.8070x; 1.2400x over previous
#include <cuda_runtime.h>
#include <cuda_bf16.h>
#include <math.h>
#include <stdint.h>

#define NMAX 100000
#define EMAX 1600000
#define DDIM 128

// ---------------- scratch (static __device__ arrays; no allocation) ----------
__device__ float g_h [NMAX * DDIM];
__device__ float g_x2[NMAX * DDIM];
__device__ float g_x3[NMAX * DDIM];
__device__ float g_u [NMAX * DDIM];
__device__ float g_v [NMAX * DDIM];
__device__ __nv_bfloat16 g_ahi[NMAX * DDIM];
__device__ __nv_bfloat16 g_alo[NMAX * DDIM];
__device__ __nv_bfloat16 g_wthi[4 * DDIM * DDIM];
__device__ __nv_bfloat16 g_wtlo[4 * DDIM * DDIM];
__device__ float4 g_asrc[NMAX];
__device__ float4 g_adst[NMAX];
__device__ int g_deg   [NMAX];
__device__ int g_rowptr[NMAX + 1];
__device__ int g_cursor[NMAX];
__device__ int g_col   [EMAX];
__device__ int g_bsums [1024];

__device__ __forceinline__ uint32_t smem_to_u32(const void* p) {
    uint32_t a;
    asm("{ .reg .u64 t; cvta.to.shared.u64 t, %1; cvt.u32.u64 %0, t; }" : "=r"(a) : "l"(p));
    return a;
}
#define SW128(off) ((off) ^ (((off) >> 3) & 0x70))

#define LDSM4(r0, r1, r2, r3, addr) \
    asm volatile("ldmatrix.sync.aligned.m8n8.x4.shared.b16 {%0,%1,%2,%3}, [%4];" \
        : "=r"(r0), "=r"(r1), "=r"(r2), "=r"(r3) : "r"(addr))

__device__ __forceinline__ void mma16816(float* d, const uint32_t* a, const uint32_t* b) {
    asm volatile(
        "mma.sync.aligned.m16n8k16.row.col.f32.bf16.bf16.f32 "
        "{%0,%1,%2,%3},{%4,%5,%6,%7},{%8,%9},{%0,%1,%2,%3};"
        : "+f"(d[0]), "+f"(d[1]), "+f"(d[2]), "+f"(d[3])
        : "r"(a[0]), "r"(a[1]), "r"(a[2]), "r"(a[3]), "r"(b[0]), "r"(b[1]));
}

// ---------------- CSR build ----------------
__global__ void k_zero_deg(int n) {
    int i = blockIdx.x * blockDim.x + threadIdx.x;
    if (i < n) g_deg[i] = 0;
}
__global__ void k_hist(const int* __restrict__ dst, int e) {
    int i = blockIdx.x * blockDim.x + threadIdx.x;
    if (i < e) atomicAdd(&g_deg[dst[i]], 1);
}
__global__ void k_scan1(int n) {
    __shared__ int sm[1024];
    int tid = threadIdx.x;
    int i = blockIdx.x * 1024 + tid;
    int v = (i < n) ? g_deg[i] : 0;
    sm[tid] = v;
    __syncthreads();
    for (int off = 1; off < 1024; off <<= 1) {
        int t = (tid >= off) ? sm[tid - off] : 0;
        __syncthreads();
        sm[tid] += t;
        __syncthreads();
    }
    if (i < n) g_rowptr[i] = sm[tid] - v;
    if (tid == 1023) g_bsums[blockIdx.x] = sm[1023];
}
__global__ void k_scan2(int nb) {
    __shared__ int sm[1024];
    int tid = threadIdx.x;
    int v = (tid < nb) ? g_bsums[tid] : 0;
    sm[tid] = v;
    __syncthreads();
    for (int off = 1; off < 1024; off <<= 1) {
        int t = (tid >= off) ? sm[tid - off] : 0;
        __syncthreads();
        sm[tid] += t;
        __syncthreads();
    }
    if (tid < nb) g_bsums[tid] = sm[tid] - v;
}
__global__ void k_scan3(int n, int e) {
    int i = blockIdx.x * 1024 + threadIdx.x;
    if (i < n) {
        int v = g_rowptr[i] + g_bsums[blockIdx.x];
        g_rowptr[i] = v;
        g_cursor[i] = v;
    }
    if (i == 0) g_rowptr[n] = e;
}
__global__ void k_scatter(const int* __restrict__ src, const int* __restrict__ dst, int e) {
    int i = blockIdx.x * blockDim.x + threadIdx.x;
    if (i < e) {
        int d = dst[i];
        int slot = atomicAdd(&g_cursor[d], 1);
        g_col[slot] = src[i];
    }
}

// ---------------- fp32 -> bf16 hi/lo splits ----------------
__global__ void k_split(const float* __restrict__ x, __nv_bfloat16* __restrict__ hi,
                        __nv_bfloat16* __restrict__ lo, int nelem2) {
    int i = blockIdx.x * blockDim.x + threadIdx.x;
    if (i < nelem2) {
        float2 v = reinterpret_cast<const float2*>(x)[i];
        __nv_bfloat162 h = __floats2bfloat162_rn(v.x, v.y);
        float r0 = v.x - __bfloat162float(h.x);
        float r1 = v.y - __bfloat162float(h.y);
        __nv_bfloat162 l = __floats2bfloat162_rn(r0, r1);
        reinterpret_cast<__nv_bfloat162*>(hi)[i] = h;
        reinterpret_cast<__nv_bfloat162*>(lo)[i] = l;
    }
}

// W [128,128] row-major -> Wt[n][k] bf16 hi/lo (K-major)
__global__ void k_wsplit(const float* __restrict__ W, __nv_bfloat16* __restrict__ hi,
                         __nv_bfloat16* __restrict__ lo) {
    int i = blockIdx.x * blockDim.x + threadIdx.x;   // 8192 pairs
    if (i < 8192) {
        int nn = i >> 6;
        int kp = (i & 63) * 2;
        float x0 = W[(size_t)kp * 128 + nn];
        float x1 = W[(size_t)(kp + 1) * 128 + nn];
        __nv_bfloat162 h = __floats2bfloat162_rn(x0, x1);
        float r0 = x0 - __bfloat162float(h.x);
        float r1 = x1 - __bfloat162float(h.y);
        __nv_bfloat162 l = __floats2bfloat162_rn(r0, r1);
        reinterpret_cast<__nv_bfloat162*>(hi)[i] = h;
        reinterpret_cast<__nv_bfloat162*>(lo)[i] = l;
    }
}

// ---------------- HMMA GEMM: C[n,128] = A[n,128] @ W[128,128] ----------------
// A given as bf16 hi/lo [n,128]; W given as Wt[n][k] bf16 hi/lo.
// Block: 128 rows x 128 cols, 512 threads (warp grid 4m x 4n, warp tile 32x32).
// K chunked in halves of 64 (SW128 swizzled smem tiles, 16KB each, 64KB total).
#define GEMM_SMEM 65536

__global__ void __launch_bounds__(512, 1) k_gemm_mma(
    const __nv_bfloat16* __restrict__ Ahi, const __nv_bfloat16* __restrict__ Alo,
    const __nv_bfloat16* __restrict__ Bhi, const __nv_bfloat16* __restrict__ Blo,
    float* __restrict__ C, int n)
{
    extern __shared__ char smem[];
    uint32_t sb = smem_to_u32(smem);
    const uint32_t sAhi = sb;
    const uint32_t sAlo = sb + 16384;
    const uint32_t sBhi = sb + 32768;
    const uint32_t sBlo = sb + 49152;

    int tid = threadIdx.x;
    int wid = tid >> 5, lane = tid & 31;
    int wm = wid & 3, wn = wid >> 2;
    int row0 = blockIdx.x * 128;

    float acc[2][4][4];
#pragma unroll
    for (int i = 0; i < 2; i++)
#pragma unroll
        for (int j = 0; j < 4; j++)
#pragma unroll
            for (int q = 0; q < 4; q++) acc[i][j][q] = 0.f;

    const uint4 zero4 = make_uint4(0, 0, 0, 0);

    for (int kh = 0; kh < 2; kh++) {
        // ---- load chunk: 4 tiles x 1024 uint4, 512 threads -> 2 per tile ----
#pragma unroll
        for (int t = 0; t < 2; t++) {
            int i = tid + t * 512;
            int r = i >> 3, o = i & 7;
            uint32_t soff = SW128((uint32_t)(r * 128 + o * 16));
            size_t aidx = ((size_t)(row0 + r) * 128 + kh * 64 + o * 8) >> 3; // uint4 idx
            size_t bidx = ((size_t)r * 128 + kh * 64 + o * 8) >> 3;
            bool av = (row0 + r) < n;
            uint4 va = av ? reinterpret_cast<const uint4*>(Ahi)[aidx] : zero4;
            uint4 vb = av ? reinterpret_cast<const uint4*>(Alo)[aidx] : zero4;
            uint4 wh = reinterpret_cast<const uint4*>(Bhi)[bidx];
            uint4 wl = reinterpret_cast<const uint4*>(Blo)[bidx];
            *reinterpret_cast<uint4*>(smem + (sAhi - sb) + soff) = va;
            *reinterpret_cast<uint4*>(smem + (sAlo - sb) + soff) = vb;
            *reinterpret_cast<uint4*>(smem + (sBhi - sb) + soff) = wh;
            *reinterpret_cast<uint4*>(smem + (sBlo - sb) + soff) = wl;
        }
        __syncthreads();

#pragma unroll
        for (int kk = 0; kk < 4; kk++) {
            int lr = lane & 15;
            int kin = kk * 16 + ((lane >> 4) << 3);   // k within 64-half
            uint32_t ahi[2][4], alo[2][4], bxh[2][4], bxl[2][4];
#pragma unroll
            for (int mf = 0; mf < 2; mf++) {
                uint32_t off = SW128((uint32_t)((wm * 32 + mf * 16 + lr) * 128 + kin * 2));
                LDSM4(ahi[mf][0], ahi[mf][1], ahi[mf][2], ahi[mf][3], sAhi + off);
                LDSM4(alo[mf][0], alo[mf][1], alo[mf][2], alo[mf][3], sAlo + off);
            }
#pragma unroll
            for (int nf = 0; nf < 2; nf++) {
                uint32_t off = SW128((uint32_t)((wn * 32 + nf * 16 + lr) * 128 + kin * 2));
                LDSM4(bxh[nf][0], bxh[nf][1], bxh[nf][2], bxh[nf][3], sBhi + off);
                LDSM4(bxl[nf][0], bxl[nf][1], bxl[nf][2], bxl[nf][3], sBlo + off);
            }
#pragma unroll
            for (int mf = 0; mf < 2; mf++) {
#pragma unroll
                for (int ns = 0; ns < 4; ns++) {
                    int g = ns >> 1, od = ns & 1;
                    uint32_t bh[2] = { bxh[g][od], bxh[g][od + 2] };
                    uint32_t bl[2] = { bxl[g][od], bxl[g][od + 2] };
                    mma16816(acc[mf][ns], ahi[mf], bh);
                    mma16816(acc[mf][ns], ahi[mf], bl);
                    mma16816(acc[mf][ns], alo[mf], bh);
                }
            }
        }
        __syncthreads();
    }

    // ---- epilogue ----
    int qrow = lane >> 2, qcol = (lane & 3) * 2;
#pragma unroll
    for (int mf = 0; mf < 2; mf++) {
#pragma unroll
        for (int ns = 0; ns < 4; ns++) {
            int r0 = row0 + wm * 32 + mf * 16 + qrow;
            int c0 = wn * 32 + ns * 8 + qcol;
            if (r0 < n)
                *reinterpret_cast<float2*>(&C[(size_t)r0 * 128 + c0]) =
                    make_float2(acc[mf][ns][0], acc[mf][ns][1]);
            if (r0 + 8 < n)
                *reinterpret_cast<float2*>(&C[(size_t)(r0 + 8) * 128 + c0]) =
                    make_float2(acc[mf][ns][2], acc[mf][ns][3]);
        }
    }
}

// ---------------- per-node alpha ----------------
__device__ __forceinline__ float warp_sum(float v) {
#pragma unroll
    for (int o = 16; o; o >>= 1) v += __shfl_xor_sync(0xffffffffu, v, o);
    return v;
}
__device__ __forceinline__ float warp_max(float v) {
#pragma unroll
    for (int o = 16; o; o >>= 1) v = fmaxf(v, __shfl_xor_sync(0xffffffffu, v, o));
    return v;
}

__global__ void k_alpha(const float* __restrict__ h,
                        const float* __restrict__ a_src,
                        const float* __restrict__ a_dst, int n)
{
    int gw = (blockIdx.x * blockDim.x + threadIdx.x) >> 5;
    int lane = threadIdx.x & 31;
    if (gw >= n) return;
    const float* hr = h + (size_t)gw * 128;
    float ps[4], pd[4];
#pragma unroll
    for (int hh = 0; hh < 4; hh++) {
        float hv = hr[hh * 32 + lane];
        ps[hh] = hv * a_src[hh * 32 + lane];
        pd[hh] = hv * a_dst[hh * 32 + lane];
    }
#pragma unroll
    for (int hh = 0; hh < 4; hh++) { ps[hh] = warp_sum(ps[hh]); pd[hh] = warp_sum(pd[hh]); }
    if (lane == 0) {
        g_asrc[gw] = make_float4(ps[0], ps[1], ps[2], ps[3]);
        g_adst[gw] = make_float4(pd[0], pd[1], pd[2], pd[3]);
    }
}

// ---------------- fused GAT aggregation + ELU + residual --------------------
__device__ __forceinline__ float lrelu(float x) { return x >= 0.f ? x : 0.2f * x; }
__device__ __forceinline__ float elu(float x)  { return x > 0.f ? x : expm1f(x); }

__global__ void k_edgeagg(const float* __restrict__ h,
                          const float* __restrict__ xprev,
                          float* __restrict__ xnext, int n)
{
    int gw = (blockIdx.x * blockDim.x + threadIdx.x) >> 5;
    int lane = threadIdx.x & 31;
    if (gw >= n) return;

    int base = g_rowptr[gw];
    int deg  = g_rowptr[gw + 1] - base;
    float4 ad = g_adst[gw];

    float m0 = -INFINITY, m1 = -INFINITY, m2 = -INFINITY, m3 = -INFINITY;
    for (int i = lane; i < deg; i += 32) {
        int s = g_col[base + i];
        float4 as = g_asrc[s];
        m0 = fmaxf(m0, lrelu(as.x + ad.x));
        m1 = fmaxf(m1, lrelu(as.y + ad.y));
        m2 = fmaxf(m2, lrelu(as.z + ad.z));
        m3 = fmaxf(m3, lrelu(as.w + ad.w));
    }
    m0 = fmaxf(warp_max(m0), 0.f);
    m1 = fmaxf(warp_max(m1), 0.f);
    m2 = fmaxf(warp_max(m2), 0.f);
    m3 = fmaxf(warp_max(m3), 0.f);

    float s0 = 0.f, s1 = 0.f, s2 = 0.f, s3 = 0.f;
    for (int i = lane; i < deg; i += 32) {
        int s = g_col[base + i];
        float4 as = g_asrc[s];
        s0 += expf(lrelu(as.x + ad.x) - m0);
        s1 += expf(lrelu(as.y + ad.y) - m1);
        s2 += expf(lrelu(as.z + ad.z) - m2);
        s3 += expf(lrelu(as.w + ad.w) - m3);
    }
    s0 = warp_sum(s0); s1 = warp_sum(s1); s2 = warp_sum(s2); s3 = warp_sum(s3);
    float i0 = 1.f / (s0 + 1e-10f);
    float i1 = 1.f / (s1 + 1e-10f);
    float i2 = 1.f / (s2 + 1e-10f);
    float i3 = 1.f / (s3 + 1e-10f);

    float a0 = 0.f, a1 = 0.f, a2 = 0.f, a3 = 0.f;
    for (int base_i = 0; base_i < deg; base_i += 32) {
        int cnt = min(32, deg - base_i);
        int mys = 0;
        float w0 = 0.f, w1 = 0.f, w2 = 0.f, w3 = 0.f;
        if (lane < cnt) {
            mys = g_col[base + base_i + lane];
            float4 as = g_asrc[mys];
            w0 = expf(lrelu(as.x + ad.x) - m0) * i0;
            w1 = expf(lrelu(as.y + ad.y) - m1) * i1;
            w2 = expf(lrelu(as.z + ad.z) - m2) * i2;
            w3 = expf(lrelu(as.w + ad.w) - m3) * i3;
        }
        for (int j = 0; j < cnt; j++) {
            int s   = __shfl_sync(0xffffffffu, mys, j);
            float c0 = __shfl_sync(0xffffffffu, w0, j);
            float c1 = __shfl_sync(0xffffffffu, w1, j);
            float c2 = __shfl_sync(0xffffffffu, w2, j);
            float c3 = __shfl_sync(0xffffffffu, w3, j);
            const float* hr = h + (size_t)s * 128;
            a0 += hr[lane]      * c0;
            a1 += hr[32 + lane] * c1;
            a2 += hr[64 + lane] * c2;
            a3 += hr[96 + lane] * c3;
        }
    }

    size_t o = (size_t)gw * 128 + lane;
    xnext[o]      = elu(a0) + xprev[o];
    xnext[o + 32] = elu(a1) + xprev[o + 32];
    xnext[o + 64] = elu(a2) + xprev[o + 64];
    xnext[o + 96] = elu(a3) + xprev[o + 96];
}

// ---------------- pair epilogue ----------------
__global__ void k_pairs(const int* __restrict__ lsrc, const int* __restrict__ ldst,
                        const float* __restrict__ b1, const float* __restrict__ w2,
                        const float* __restrict__ b2, float* __restrict__ out, int p)
{
    int gw = (blockIdx.x * blockDim.x + threadIdx.x) >> 5;
    int lane = threadIdx.x & 31;
    if (gw >= p) return;
    const float* up = g_u + (size_t)lsrc[gw] * 128;
    const float* vp = g_v + (size_t)ldst[gw] * 128;
    float t = 0.f;
#pragma unroll
    for (int hh = 0; hh < 4; hh++) {
        int k = hh * 32 + lane;
        float hid = up[k] + vp[k] + b1[k];
        hid = fmaxf(hid, 0.f);
        t += hid * w2[k];
    }
    t = warp_sum(t);
    if (lane == 0) out[gw] = t + b2[0];
}

// ---------------- driver ----------------
extern "C" void kernel_launch(void* const* d_in, const int* in_sizes, int n_in,
                              void* d_out, int out_size)
{
    const float* embed  = (const float*)d_in[0];
    const float* W1     = (const float*)d_in[1];
    const float* a_src1 = (const float*)d_in[2];
    const float* a_dst1 = (const float*)d_in[3];
    const float* W2     = (const float*)d_in[4];
    const float* a_src2 = (const float*)d_in[5];
    const float* a_dst2 = (const float*)d_in[6];
    const float* lp_w1  = (const float*)d_in[7];
    const float* lp_b1  = (const float*)d_in[8];
    const float* lp_w2  = (const float*)d_in[9];
    const float* lp_b2  = (const float*)d_in[10];
    const int*   eidx   = (const int*)d_in[11];
    const int*   lsrc   = (const int*)d_in[12];
    const int*   ldst   = (const int*)d_in[13];
    float* out = (float*)d_out;

    const int N = in_sizes[0] / DDIM;
    const int E = in_sizes[11] / 2;
    const int P = in_sizes[12];
    const int* esrc = eidx;
    const int* edst = eidx + E;

    float* hbuf; cudaGetSymbolAddress((void**)&hbuf, g_h);
    float* x2;   cudaGetSymbolAddress((void**)&x2,   g_x2);
    float* x3;   cudaGetSymbolAddress((void**)&x3,   g_x3);
    float* ub;   cudaGetSymbolAddress((void**)&ub,   g_u);
    float* vb;   cudaGetSymbolAddress((void**)&vb,   g_v);
    __nv_bfloat16* ahi; cudaGetSymbolAddress((void**)&ahi, g_ahi);
    __nv_bfloat16* alo; cudaGetSymbolAddress((void**)&alo, g_alo);
    __nv_bfloat16* wthi; cudaGetSymbolAddress((void**)&wthi, g_wthi);
    __nv_bfloat16* wtlo; cudaGetSymbolAddress((void**)&wtlo, g_wtlo);

    cudaFuncSetAttribute(k_gemm_mma, cudaFuncAttributeMaxDynamicSharedMemorySize, GEMM_SMEM);

    const int T = 256;
    int nbN  = (N + T - 1) / T;
    int nbE  = (E + T - 1) / T;
    int nbS  = (N + 1023) / 1024;
    int nbW  = (N * 32 + T - 1) / T;
    int nbPW = (P * 32 + T - 1) / T;
    int nbG  = (N + 127) / 128;
    int nbSp = (N * DDIM / 2 + T - 1) / T;
    const int WSZ = DDIM * DDIM;

    // CSR by dst (shared by both layers)
    k_zero_deg<<<nbN, T>>>(N);
    k_hist<<<nbE, T>>>(edst, E);
    k_scan1<<<nbS, 1024>>>(N);
    k_scan2<<<1, 1024>>>(nbS);
    k_scan3<<<nbS, 1024>>>(N, E);
    k_scatter<<<nbE, T>>>(esrc, edst, E);

    // weight transposes/splits
    k_wsplit<<<32, 256>>>(W1,              wthi + 0 * WSZ, wtlo + 0 * WSZ);
    k_wsplit<<<32, 256>>>(W2,              wthi + 1 * WSZ, wtlo + 1 * WSZ);
    k_wsplit<<<32, 256>>>(lp_w1,           wthi + 2 * WSZ, wtlo + 2 * WSZ);
    k_wsplit<<<32, 256>>>(lp_w1 + 128*128, wthi + 3 * WSZ, wtlo + 3 * WSZ);

    // layer 1
    k_split<<<nbSp, T>>>(embed, ahi, alo, N * DDIM / 2);
    k_gemm_mma<<<nbG, 512, GEMM_SMEM>>>(ahi, alo, wthi + 0 * WSZ, wtlo + 0 * WSZ, hbuf, N);
    k_alpha<<<nbW, T>>>(hbuf, a_src1, a_dst1, N);
    k_edgeagg<<<nbW, T>>>(hbuf, embed, x2, N);

    // layer 2
    k_split<<<nbSp, T>>>(x2, ahi, alo, N * DDIM / 2);
    k_gemm_mma<<<nbG, 512, GEMM_SMEM>>>(ahi, alo, wthi + 1 * WSZ, wtlo + 1 * WSZ, hbuf, N);
    k_alpha<<<nbW, T>>>(hbuf, a_src2, a_dst2, N);
    k_edgeagg<<<nbW, T>>>(hbuf, x2, x3, N);

    // link predictor: u = z @ lp_w1[:128], v = z @ lp_w1[128:]
    k_split<<<nbSp, T>>>(x3, ahi, alo, N * DDIM / 2);
    k_gemm_mma<<<nbG, 512, GEMM_SMEM>>>(ahi, alo, wthi + 2 * WSZ, wtlo + 2 * WSZ, ub, N);
    k_gemm_mma<<<nbG, 512, GEMM_SMEM>>>(ahi, alo, wthi + 3 * WSZ, wtlo + 3 * WSZ, vb, N);
    k_pairs<<<nbPW, T>>>(lsrc, ldst, lp_b1, lp_w2, lp_b2, out, P);
}

// round 5
// speedup vs baseline: 1.9715x; 1.0910x over previous
#include <cuda_runtime.h>
#include <cuda_bf16.h>
#include <math.h>
#include <stdint.h>

#define NMAX 100000
#define EMAX 1600000
#define DDIM 128

// ---------------- scratch (static __device__ arrays; no allocation) ----------
__device__ float g_h [NMAX * DDIM];
__device__ float g_x2[NMAX * DDIM];
__device__ float g_u [NMAX * DDIM];
__device__ float g_v [NMAX * DDIM];
__device__ __nv_bfloat16 g_ahi[NMAX * DDIM];
__device__ __nv_bfloat16 g_alo[NMAX * DDIM];
__device__ __nv_bfloat16 g_wthi[4 * DDIM * DDIM];
__device__ __nv_bfloat16 g_wtlo[4 * DDIM * DDIM];
__device__ float4 g_asrc[NMAX];
__device__ float4 g_adst[NMAX];
__device__ float4 g_ew  [EMAX];      // per-edge logits -> unnormalized softmax
__device__ int g_deg   [NMAX];
__device__ int g_rowptr[NMAX + 1];
__device__ int g_cursor[NMAX];
__device__ int g_col   [EMAX];
__device__ int g_bsums [1024];

__device__ __forceinline__ uint32_t smem_to_u32(const void* p) {
    uint32_t a;
    asm("{ .reg .u64 t; cvta.to.shared.u64 t, %1; cvt.u32.u64 %0, t; }" : "=r"(a) : "l"(p));
    return a;
}
#define SW128(off) ((off) ^ (((off) >> 3) & 0x70))

#define LDSM4(r0, r1, r2, r3, addr) \
    asm volatile("ldmatrix.sync.aligned.m8n8.x4.shared.b16 {%0,%1,%2,%3}, [%4];" \
        : "=r"(r0), "=r"(r1), "=r"(r2), "=r"(r3) : "r"(addr))

__device__ __forceinline__ void mma16816(float* d, const uint32_t* a, const uint32_t* b) {
    asm volatile(
        "mma.sync.aligned.m16n8k16.row.col.f32.bf16.bf16.f32 "
        "{%0,%1,%2,%3},{%4,%5,%6,%7},{%8,%9},{%0,%1,%2,%3};"
        : "+f"(d[0]), "+f"(d[1]), "+f"(d[2]), "+f"(d[3])
        : "r"(a[0]), "r"(a[1]), "r"(a[2]), "r"(a[3]), "r"(b[0]), "r"(b[1]));
}

// ---------------- CSR build ----------------
__global__ void k_zero_deg(int n) {
    int i = blockIdx.x * blockDim.x + threadIdx.x;
    if (i < n) g_deg[i] = 0;
}
__global__ void k_hist(const int* __restrict__ dst, int e) {
    int i = blockIdx.x * blockDim.x + threadIdx.x;
    if (i < e) atomicAdd(&g_deg[dst[i]], 1);
}
__global__ void k_scan1(int n) {
    __shared__ int sm[1024];
    int tid = threadIdx.x;
    int i = blockIdx.x * 1024 + tid;
    int v = (i < n) ? g_deg[i] : 0;
    sm[tid] = v;
    __syncthreads();
    for (int off = 1; off < 1024; off <<= 1) {
        int t = (tid >= off) ? sm[tid - off] : 0;
        __syncthreads();
        sm[tid] += t;
        __syncthreads();
    }
    if (i < n) g_rowptr[i] = sm[tid] - v;
    if (tid == 1023) g_bsums[blockIdx.x] = sm[1023];
}
__global__ void k_scan2(int nb) {
    __shared__ int sm[1024];
    int tid = threadIdx.x;
    int v = (tid < nb) ? g_bsums[tid] : 0;
    sm[tid] = v;
    __syncthreads();
    for (int off = 1; off < 1024; off <<= 1) {
        int t = (tid >= off) ? sm[tid - off] : 0;
        __syncthreads();
        sm[tid] += t;
        __syncthreads();
    }
    if (tid < nb) g_bsums[tid] = sm[tid] - v;
}
__global__ void k_scan3(int n, int e) {
    int i = blockIdx.x * 1024 + threadIdx.x;
    if (i < n) {
        int v = g_rowptr[i] + g_bsums[blockIdx.x];
        g_rowptr[i] = v;
        g_cursor[i] = v;
    }
    if (i == 0) g_rowptr[n] = e;
}
__global__ void k_scatter(const int* __restrict__ src, const int* __restrict__ dst, int e) {
    int i = blockIdx.x * blockDim.x + threadIdx.x;
    if (i < e) {
        int d = dst[i];
        int slot = atomicAdd(&g_cursor[d], 1);
        g_col[slot] = src[i];
    }
}

// ---------------- fp32 -> bf16 hi/lo splits ----------------
__global__ void k_split(const float* __restrict__ x, __nv_bfloat16* __restrict__ hi,
                        __nv_bfloat16* __restrict__ lo, int nelem2) {
    int i = blockIdx.x * blockDim.x + threadIdx.x;
    if (i < nelem2) {
        float2 v = reinterpret_cast<const float2*>(x)[i];
        __nv_bfloat162 h = __floats2bfloat162_rn(v.x, v.y);
        float r0 = v.x - __bfloat162float(h.x);
        float r1 = v.y - __bfloat162float(h.y);
        __nv_bfloat162 l = __floats2bfloat162_rn(r0, r1);
        reinterpret_cast<__nv_bfloat162*>(hi)[i] = h;
        reinterpret_cast<__nv_bfloat162*>(lo)[i] = l;
    }
}

// W [128,128] row-major -> Wt[n][k] bf16 hi/lo (K-major)
__global__ void k_wsplit(const float* __restrict__ W, __nv_bfloat16* __restrict__ hi,
                         __nv_bfloat16* __restrict__ lo) {
    int i = blockIdx.x * blockDim.x + threadIdx.x;   // 8192 pairs
    if (i < 8192) {
        int nn = i >> 6;
        int kp = (i & 63) * 2;
        float x0 = W[(size_t)kp * 128 + nn];
        float x1 = W[(size_t)(kp + 1) * 128 + nn];
        __nv_bfloat162 h = __floats2bfloat162_rn(x0, x1);
        float r0 = x0 - __bfloat162float(h.x);
        float r1 = x1 - __bfloat162float(h.y);
        __nv_bfloat162 l = __floats2bfloat162_rn(r0, r1);
        reinterpret_cast<__nv_bfloat162*>(hi)[i] = h;
        reinterpret_cast<__nv_bfloat162*>(lo)[i] = l;
    }
}

// ---------------- HMMA GEMM: C[n,128] = A[n,128] @ W[128,128] ----------------
// Full-K resident: 4 bf16 tiles of 32KB (two SW128 64-k halves each) = 128KB.
#define GEMM_SMEM 131072

__global__ void __launch_bounds__(512, 1) k_gemm_mma(
    const __nv_bfloat16* __restrict__ Ahi, const __nv_bfloat16* __restrict__ Alo,
    const __nv_bfloat16* __restrict__ Bhi, const __nv_bfloat16* __restrict__ Blo,
    float* __restrict__ C, int n)
{
    extern __shared__ char smem[];
    uint32_t sb = smem_to_u32(smem);
    const uint32_t sAhi = sb;
    const uint32_t sAlo = sb + 32768;
    const uint32_t sBhi = sb + 65536;
    const uint32_t sBlo = sb + 98304;

    int tid = threadIdx.x;
    int wid = tid >> 5, lane = tid & 31;
    int wm = wid & 3, wn = wid >> 2;
    int row0 = blockIdx.x * 128;

    float acc[2][4][4];
#pragma unroll
    for (int i = 0; i < 2; i++)
#pragma unroll
        for (int j = 0; j < 4; j++)
#pragma unroll
            for (int q = 0; q < 4; q++) acc[i][j][q] = 0.f;

    const uint4 zero4 = make_uint4(0, 0, 0, 0);

    // ---- load ALL K: per array 2048 uint4, 512 threads -> 4 each ----
#pragma unroll
    for (int t = 0; t < 4; t++) {
        int i = tid + t * 512;
        int r = i >> 4;                 // row 0..127
        int o = i & 15;                 // 16B group 0..15 across K=128
        int kh = o >> 3, oo = o & 7;
        uint32_t soff = (uint32_t)(kh * 16384) + SW128((uint32_t)(r * 128 + oo * 16));
        size_t aidx = ((size_t)(row0 + r) * 128 + kh * 64 + oo * 8) >> 3;
        size_t bidx = ((size_t)r * 128 + kh * 64 + oo * 8) >> 3;
        bool av = (row0 + r) < n;
        uint4 va = av ? reinterpret_cast<const uint4*>(Ahi)[aidx] : zero4;
        uint4 vb = av ? reinterpret_cast<const uint4*>(Alo)[aidx] : zero4;
        uint4 wh = reinterpret_cast<const uint4*>(Bhi)[bidx];
        uint4 wl = reinterpret_cast<const uint4*>(Blo)[bidx];
        *reinterpret_cast<uint4*>(smem + (sAhi - sb) + soff) = va;
        *reinterpret_cast<uint4*>(smem + (sAlo - sb) + soff) = vb;
        *reinterpret_cast<uint4*>(smem + (sBhi - sb) + soff) = wh;
        *reinterpret_cast<uint4*>(smem + (sBlo - sb) + soff) = wl;
    }
    __syncthreads();

#pragma unroll
    for (int kh = 0; kh < 2; kh++) {
        uint32_t hoff = (uint32_t)(kh * 16384);
#pragma unroll
        for (int kk = 0; kk < 4; kk++) {
            int lr = lane & 15;
            int kin = kk * 16 + ((lane >> 4) << 3);
            uint32_t ahi[2][4], alo[2][4], bxh[2][4], bxl[2][4];
#pragma unroll
            for (int mf = 0; mf < 2; mf++) {
                uint32_t off = hoff + SW128((uint32_t)((wm * 32 + mf * 16 + lr) * 128 + kin * 2));
                LDSM4(ahi[mf][0], ahi[mf][1], ahi[mf][2], ahi[mf][3], sAhi + off);
                LDSM4(alo[mf][0], alo[mf][1], alo[mf][2], alo[mf][3], sAlo + off);
            }
#pragma unroll
            for (int nf = 0; nf < 2; nf++) {
                uint32_t off = hoff + SW128((uint32_t)((wn * 32 + nf * 16 + lr) * 128 + kin * 2));
                LDSM4(bxh[nf][0], bxh[nf][1], bxh[nf][2], bxh[nf][3], sBhi + off);
                LDSM4(bxl[nf][0], bxl[nf][1], bxl[nf][2], bxl[nf][3], sBlo + off);
            }
#pragma unroll
            for (int mf = 0; mf < 2; mf++) {
#pragma unroll
                for (int ns = 0; ns < 4; ns++) {
                    int g = ns >> 1, od = ns & 1;
                    uint32_t bh[2] = { bxh[g][od], bxh[g][od + 2] };
                    uint32_t bl[2] = { bxl[g][od], bxl[g][od + 2] };
                    mma16816(acc[mf][ns], ahi[mf], bh);
                    mma16816(acc[mf][ns], ahi[mf], bl);
                    mma16816(acc[mf][ns], alo[mf], bh);
                }
            }
        }
    }

    // ---- epilogue ----
    int qrow = lane >> 2, qcol = (lane & 3) * 2;
#pragma unroll
    for (int mf = 0; mf < 2; mf++) {
#pragma unroll
        for (int ns = 0; ns < 4; ns++) {
            int r0 = row0 + wm * 32 + mf * 16 + qrow;
            int c0 = wn * 32 + ns * 8 + qcol;
            if (r0 < n)
                *reinterpret_cast<float2*>(&C[(size_t)r0 * 128 + c0]) =
                    make_float2(acc[mf][ns][0], acc[mf][ns][1]);
            if (r0 + 8 < n)
                *reinterpret_cast<float2*>(&C[(size_t)(r0 + 8) * 128 + c0]) =
                    make_float2(acc[mf][ns][2], acc[mf][ns][3]);
        }
    }
}

// ---------------- per-node alpha ----------------
__device__ __forceinline__ float warp_sum(float v) {
#pragma unroll
    for (int o = 16; o; o >>= 1) v += __shfl_xor_sync(0xffffffffu, v, o);
    return v;
}
__device__ __forceinline__ float warp_max(float v) {
#pragma unroll
    for (int o = 16; o; o >>= 1) v = fmaxf(v, __shfl_xor_sync(0xffffffffu, v, o));
    return v;
}

__global__ void k_alpha(const float* __restrict__ h,
                        const float* __restrict__ a_src,
                        const float* __restrict__ a_dst, int n)
{
    int gw = (blockIdx.x * blockDim.x + threadIdx.x) >> 5;
    int lane = threadIdx.x & 31;
    if (gw >= n) return;
    const float* hr = h + (size_t)gw * 128;
    float ps[4], pd[4];
#pragma unroll
    for (int hh = 0; hh < 4; hh++) {
        float hv = hr[hh * 32 + lane];
        ps[hh] = hv * a_src[hh * 32 + lane];
        pd[hh] = hv * a_dst[hh * 32 + lane];
    }
#pragma unroll
    for (int hh = 0; hh < 4; hh++) { ps[hh] = warp_sum(ps[hh]); pd[hh] = warp_sum(pd[hh]); }
    if (lane == 0) {
        g_asrc[gw] = make_float4(ps[0], ps[1], ps[2], ps[3]);
        g_adst[gw] = make_float4(pd[0], pd[1], pd[2], pd[3]);
    }
}

// ---------------- fused GAT aggregation + ELU + residual + bf16 split -------
__device__ __forceinline__ float lrelu(float x) { return x >= 0.f ? x : 0.2f * x; }
__device__ __forceinline__ float elu(float x)  { return x > 0.f ? x : expm1f(x); }

// writes: xnext (fp32, optional), hi/lo bf16 split (optional)
__global__ void k_edgeagg(const float* __restrict__ h,
                          const float* __restrict__ xprev,
                          float* __restrict__ xnext,
                          __nv_bfloat16* __restrict__ hi,
                          __nv_bfloat16* __restrict__ lo, int n)
{
    int gw = (blockIdx.x * blockDim.x + threadIdx.x) >> 5;
    int lane = threadIdx.x & 31;
    if (gw >= n) return;

    int base = g_rowptr[gw];
    int deg  = g_rowptr[gw + 1] - base;
    float4 ad = g_adst[gw];

    // pass 1: compute logits, store to g_ew, track per-head max (clamped at 0)
    float m0 = -INFINITY, m1 = -INFINITY, m2 = -INFINITY, m3 = -INFINITY;
    for (int i = lane; i < deg; i += 32) {
        int s = g_col[base + i];
        float4 as = g_asrc[s];
        float e0 = lrelu(as.x + ad.x);
        float e1 = lrelu(as.y + ad.y);
        float e2 = lrelu(as.z + ad.z);
        float e3 = lrelu(as.w + ad.w);
        g_ew[base + i] = make_float4(e0, e1, e2, e3);
        m0 = fmaxf(m0, e0); m1 = fmaxf(m1, e1);
        m2 = fmaxf(m2, e2); m3 = fmaxf(m3, e3);
    }
    m0 = fmaxf(warp_max(m0), 0.f);
    m1 = fmaxf(warp_max(m1), 0.f);
    m2 = fmaxf(warp_max(m2), 0.f);
    m3 = fmaxf(warp_max(m3), 0.f);

    // pass 2: p = exp(e - m); store back; accumulate sums
    float s0 = 0.f, s1 = 0.f, s2 = 0.f, s3 = 0.f;
    for (int i = lane; i < deg; i += 32) {
        float4 e = g_ew[base + i];
        float p0 = expf(e.x - m0);
        float p1 = expf(e.y - m1);
        float p2 = expf(e.z - m2);
        float p3 = expf(e.w - m3);
        g_ew[base + i] = make_float4(p0, p1, p2, p3);
        s0 += p0; s1 += p1; s2 += p2; s3 += p3;
    }
    s0 = warp_sum(s0); s1 = warp_sum(s1); s2 = warp_sum(s2); s3 = warp_sum(s3);
    float i0 = 1.f / (s0 + 1e-10f);
    float i1 = 1.f / (s1 + 1e-10f);
    float i2 = 1.f / (s2 + 1e-10f);
    float i3 = 1.f / (s3 + 1e-10f);

    // pass 3: weighted aggregation
    float a0 = 0.f, a1 = 0.f, a2 = 0.f, a3 = 0.f;
    for (int base_i = 0; base_i < deg; base_i += 32) {
        int cnt = min(32, deg - base_i);
        int mys = 0;
        float w0 = 0.f, w1 = 0.f, w2 = 0.f, w3 = 0.f;
        if (lane < cnt) {
            mys = g_col[base + base_i + lane];
            float4 p = g_ew[base + base_i + lane];
            w0 = p.x * i0; w1 = p.y * i1; w2 = p.z * i2; w3 = p.w * i3;
        }
        for (int j = 0; j < cnt; j++) {
            int s   = __shfl_sync(0xffffffffu, mys, j);
            float c0 = __shfl_sync(0xffffffffu, w0, j);
            float c1 = __shfl_sync(0xffffffffu, w1, j);
            float c2 = __shfl_sync(0xffffffffu, w2, j);
            float c3 = __shfl_sync(0xffffffffu, w3, j);
            const float* hr = h + (size_t)s * 128;
            a0 += hr[lane]      * c0;
            a1 += hr[32 + lane] * c1;
            a2 += hr[64 + lane] * c2;
            a3 += hr[96 + lane] * c3;
        }
    }

    size_t o = (size_t)gw * 128 + lane;
    float v0 = elu(a0) + xprev[o];
    float v1 = elu(a1) + xprev[o + 32];
    float v2 = elu(a2) + xprev[o + 64];
    float v3 = elu(a3) + xprev[o + 96];
    if (xnext) {
        xnext[o]      = v0;
        xnext[o + 32] = v1;
        xnext[o + 64] = v2;
        xnext[o + 96] = v3;
    }
    if (hi) {
        float vv[4] = { v0, v1, v2, v3 };
#pragma unroll
        for (int q = 0; q < 4; q++) {
            __nv_bfloat16 hb = __float2bfloat16_rn(vv[q]);
            __nv_bfloat16 lb = __float2bfloat16_rn(vv[q] - __bfloat162float(hb));
            hi[o + q * 32] = hb;
            lo[o + q * 32] = lb;
        }
    }
}

// ---------------- pair epilogue ----------------
__global__ void k_pairs(const int* __restrict__ lsrc, const int* __restrict__ ldst,
                        const float* __restrict__ b1, const float* __restrict__ w2,
                        const float* __restrict__ b2, float* __restrict__ out, int p)
{
    int gw = (blockIdx.x * blockDim.x + threadIdx.x) >> 5;
    int lane = threadIdx.x & 31;
    if (gw >= p) return;
    const float* up = g_u + (size_t)lsrc[gw] * 128;
    const float* vp = g_v + (size_t)ldst[gw] * 128;
    float t = 0.f;
#pragma unroll
    for (int hh = 0; hh < 4; hh++) {
        int k = hh * 32 + lane;
        float hid = up[k] + vp[k] + b1[k];
        hid = fmaxf(hid, 0.f);
        t += hid * w2[k];
    }
    t = warp_sum(t);
    if (lane == 0) out[gw] = t + b2[0];
}

// ---------------- driver ----------------
extern "C" void kernel_launch(void* const* d_in, const int* in_sizes, int n_in,
                              void* d_out, int out_size)
{
    const float* embed  = (const float*)d_in[0];
    const float* W1     = (const float*)d_in[1];
    const float* a_src1 = (const float*)d_in[2];
    const float* a_dst1 = (const float*)d_in[3];
    const float* W2     = (const float*)d_in[4];
    const float* a_src2 = (const float*)d_in[5];
    const float* a_dst2 = (const float*)d_in[6];
    const float* lp_w1  = (const float*)d_in[7];
    const float* lp_b1  = (const float*)d_in[8];
    const float* lp_w2  = (const float*)d_in[9];
    const float* lp_b2  = (const float*)d_in[10];
    const int*   eidx   = (const int*)d_in[11];
    const int*   lsrc   = (const int*)d_in[12];
    const int*   ldst   = (const int*)d_in[13];
    float* out = (float*)d_out;

    const int N = in_sizes[0] / DDIM;
    const int E = in_sizes[11] / 2;
    const int P = in_sizes[12];
    const int* esrc = eidx;
    const int* edst = eidx + E;

    float* hbuf; cudaGetSymbolAddress((void**)&hbuf, g_h);
    float* x2;   cudaGetSymbolAddress((void**)&x2,   g_x2);
    float* ub;   cudaGetSymbolAddress((void**)&ub,   g_u);
    float* vb;   cudaGetSymbolAddress((void**)&vb,   g_v);
    __nv_bfloat16* ahi; cudaGetSymbolAddress((void**)&ahi, g_ahi);
    __nv_bfloat16* alo; cudaGetSymbolAddress((void**)&alo, g_alo);
    __nv_bfloat16* wthi; cudaGetSymbolAddress((void**)&wthi, g_wthi);
    __nv_bfloat16* wtlo; cudaGetSymbolAddress((void**)&wtlo, g_wtlo);

    cudaFuncSetAttribute(k_gemm_mma, cudaFuncAttributeMaxDynamicSharedMemorySize, GEMM_SMEM);

    const int T = 256;
    int nbN  = (N + T - 1) / T;
    int nbE  = (E + T - 1) / T;
    int nbS  = (N + 1023) / 1024;
    int nbW  = (N * 32 + T - 1) / T;
    int nbPW = (P * 32 + T - 1) / T;
    int nbG  = (N + 127) / 128;
    int nbSp = (N * DDIM / 2 + T - 1) / T;
    const int WSZ = DDIM * DDIM;

    // CSR by dst (shared by both layers)
    k_zero_deg<<<nbN, T>>>(N);
    k_hist<<<nbE, T>>>(edst, E);
    k_scan1<<<nbS, 1024>>>(N);
    k_scan2<<<1, 1024>>>(nbS);
    k_scan3<<<nbS, 1024>>>(N, E);
    k_scatter<<<nbE, T>>>(esrc, edst, E);

    // weight transposes/splits
    k_wsplit<<<32, 256>>>(W1,              wthi + 0 * WSZ, wtlo + 0 * WSZ);
    k_wsplit<<<32, 256>>>(W2,              wthi + 1 * WSZ, wtlo + 1 * WSZ);
    k_wsplit<<<32, 256>>>(lp_w1,           wthi + 2 * WSZ, wtlo + 2 * WSZ);
    k_wsplit<<<32, 256>>>(lp_w1 + 128*128, wthi + 3 * WSZ, wtlo + 3 * WSZ);

    // layer 1
    k_split<<<nbSp, T>>>(embed, ahi, alo, N * DDIM / 2);
    k_gemm_mma<<<nbG, 512, GEMM_SMEM>>>(ahi, alo, wthi + 0 * WSZ, wtlo + 0 * WSZ, hbuf, N);
    k_alpha<<<nbW, T>>>(hbuf, a_src1, a_dst1, N);
    k_edgeagg<<<nbW, T>>>(hbuf, embed, x2, ahi, alo, N);   // x2 + its bf16 split

    // layer 2
    k_gemm_mma<<<nbG, 512, GEMM_SMEM>>>(ahi, alo, wthi + 1 * WSZ, wtlo + 1 * WSZ, hbuf, N);
    k_alpha<<<nbW, T>>>(hbuf, a_src2, a_dst2, N);
    k_edgeagg<<<nbW, T>>>(hbuf, x2, nullptr, ahi, alo, N); // z only as bf16 split

    // link predictor: u = z @ lp_w1[:128], v = z @ lp_w1[128:]
    k_gemm_mma<<<nbG, 512, GEMM_SMEM>>>(ahi, alo, wthi + 2 * WSZ, wtlo + 2 * WSZ, ub, N);
    k_gemm_mma<<<nbG, 512, GEMM_SMEM>>>(ahi, alo, wthi + 3 * WSZ, wtlo + 3 * WSZ, vb, N);
    k_pairs<<<nbPW, T>>>(lsrc, ldst, lp_b1, lp_w2, lp_b2, out, P);
}

// round 6
// speedup vs baseline: 2.5325x; 1.2845x over previous
#include <cuda_runtime.h>
#include <cuda_bf16.h>
#include <math.h>
#include <stdint.h>

#define NMAX 100000
#define EMAX 1600000
#define DDIM 128

// ---------------- scratch (static __device__ arrays; no allocation) ----------
__device__ float g_h [NMAX * DDIM];
__device__ float g_x2[NMAX * DDIM];
__device__ float g_u [NMAX * DDIM];
__device__ float g_v [NMAX * DDIM];
__device__ __nv_bfloat16 g_ahi[NMAX * DDIM];
__device__ __nv_bfloat16 g_alo[NMAX * DDIM];
__device__ __nv_bfloat16 g_wthi[4 * DDIM * DDIM];
__device__ __nv_bfloat16 g_wtlo[4 * DDIM * DDIM];
__device__ float4 g_asrc[NMAX];
__device__ float4 g_adst[NMAX];
__device__ float4 g_ew  [EMAX];      // per-edge unnormalized softmax p=exp(e)
__device__ int g_deg   [NMAX];
__device__ int g_rowptr[NMAX + 1];
__device__ int g_cursor[NMAX];
__device__ int g_col   [EMAX];
__device__ int g_bsums [1024];

__device__ __forceinline__ uint32_t smem_to_u32(const void* p) {
    uint32_t a;
    asm("{ .reg .u64 t; cvta.to.shared.u64 t, %1; cvt.u32.u64 %0, t; }" : "=r"(a) : "l"(p));
    return a;
}
#define SW128(off) ((off) ^ (((off) >> 3) & 0x70))

#define LDSM4(r0, r1, r2, r3, addr) \
    asm volatile("ldmatrix.sync.aligned.m8n8.x4.shared.b16 {%0,%1,%2,%3}, [%4];" \
        : "=r"(r0), "=r"(r1), "=r"(r2), "=r"(r3) : "r"(addr))

__device__ __forceinline__ void mma16816(float* d, const uint32_t* a, const uint32_t* b) {
    asm volatile(
        "mma.sync.aligned.m16n8k16.row.col.f32.bf16.bf16.f32 "
        "{%0,%1,%2,%3},{%4,%5,%6,%7},{%8,%9},{%0,%1,%2,%3};"
        : "+f"(d[0]), "+f"(d[1]), "+f"(d[2]), "+f"(d[3])
        : "r"(a[0]), "r"(a[1]), "r"(a[2]), "r"(a[3]), "r"(b[0]), "r"(b[1]));
}

// ---------------- CSR build ----------------
__global__ void k_zero_deg(int n) {
    int i = blockIdx.x * blockDim.x + threadIdx.x;
    if (i < n) g_deg[i] = 0;
}
__global__ void k_hist(const int* __restrict__ dst, int e) {
    int i = blockIdx.x * blockDim.x + threadIdx.x;
    if (i < e) atomicAdd(&g_deg[dst[i]], 1);
}
__global__ void k_scan1(int n) {
    __shared__ int sm[1024];
    int tid = threadIdx.x;
    int i = blockIdx.x * 1024 + tid;
    int v = (i < n) ? g_deg[i] : 0;
    sm[tid] = v;
    __syncthreads();
    for (int off = 1; off < 1024; off <<= 1) {
        int t = (tid >= off) ? sm[tid - off] : 0;
        __syncthreads();
        sm[tid] += t;
        __syncthreads();
    }
    if (i < n) g_rowptr[i] = sm[tid] - v;
    if (tid == 1023) g_bsums[blockIdx.x] = sm[1023];
}
__global__ void k_scan2(int nb) {
    __shared__ int sm[1024];
    int tid = threadIdx.x;
    int v = (tid < nb) ? g_bsums[tid] : 0;
    sm[tid] = v;
    __syncthreads();
    for (int off = 1; off < 1024; off <<= 1) {
        int t = (tid >= off) ? sm[tid - off] : 0;
        __syncthreads();
        sm[tid] += t;
        __syncthreads();
    }
    if (tid < nb) g_bsums[tid] = sm[tid] - v;
}
__global__ void k_scan3(int n, int e) {
    int i = blockIdx.x * 1024 + threadIdx.x;
    if (i < n) {
        int v = g_rowptr[i] + g_bsums[blockIdx.x];
        g_rowptr[i] = v;
        g_cursor[i] = v;
    }
    if (i == 0) g_rowptr[n] = e;
}
__global__ void k_scatter(const int* __restrict__ src, const int* __restrict__ dst, int e) {
    int i = blockIdx.x * blockDim.x + threadIdx.x;
    if (i < e) {
        int d = dst[i];
        int slot = atomicAdd(&g_cursor[d], 1);
        g_col[slot] = src[i];
    }
}

// W [128,128] row-major -> Wt[n][k] bf16 hi/lo (K-major)
__global__ void k_wsplit(const float* __restrict__ W, __nv_bfloat16* __restrict__ hi,
                         __nv_bfloat16* __restrict__ lo) {
    int i = blockIdx.x * blockDim.x + threadIdx.x;   // 8192 pairs
    if (i < 8192) {
        int nn = i >> 6;
        int kp = (i & 63) * 2;
        float x0 = W[(size_t)kp * 128 + nn];
        float x1 = W[(size_t)(kp + 1) * 128 + nn];
        __nv_bfloat162 h = __floats2bfloat162_rn(x0, x1);
        float r0 = x0 - __bfloat162float(h.x);
        float r1 = x1 - __bfloat162float(h.y);
        __nv_bfloat162 l = __floats2bfloat162_rn(r0, r1);
        reinterpret_cast<__nv_bfloat162*>(hi)[i] = h;
        reinterpret_cast<__nv_bfloat162*>(lo)[i] = l;
    }
}

// ---------------- HMMA GEMM: C[n,128] = A[n,128] @ W[128,128] ----------------
// Full-K resident: 4 bf16 tiles of 32KB (two SW128 64-k halves each) = 128KB.
// If Af != nullptr, A is fp32 and split to hi/lo during the smem fill.
#define GEMM_SMEM 131072

__global__ void __launch_bounds__(512, 1) k_gemm_mma(
    const float* __restrict__ Af,
    const __nv_bfloat16* __restrict__ Ahi, const __nv_bfloat16* __restrict__ Alo,
    const __nv_bfloat16* __restrict__ Bhi, const __nv_bfloat16* __restrict__ Blo,
    float* __restrict__ C, int n)
{
    extern __shared__ char smem[];
    uint32_t sb = smem_to_u32(smem);
    const uint32_t sAhi = sb;
    const uint32_t sAlo = sb + 32768;
    const uint32_t sBhi = sb + 65536;
    const uint32_t sBlo = sb + 98304;

    int tid = threadIdx.x;
    int wid = tid >> 5, lane = tid & 31;
    int wm = wid & 3, wn = wid >> 2;
    int row0 = blockIdx.x * 128;

    float acc[2][4][4];
#pragma unroll
    for (int i = 0; i < 2; i++)
#pragma unroll
        for (int j = 0; j < 4; j++)
#pragma unroll
            for (int q = 0; q < 4; q++) acc[i][j][q] = 0.f;

    const uint4 zero4 = make_uint4(0, 0, 0, 0);

    // ---- load ALL K: per array 2048 uint4, 512 threads -> 4 each ----
#pragma unroll
    for (int t = 0; t < 4; t++) {
        int i = tid + t * 512;
        int r = i >> 4;                 // row 0..127
        int o = i & 15;                 // 16B group 0..15 across K=128
        int kh = o >> 3, oo = o & 7;
        uint32_t soff = (uint32_t)(kh * 16384) + SW128((uint32_t)(r * 128 + oo * 16));
        size_t elem = (size_t)(row0 + r) * 128 + kh * 64 + oo * 8;
        size_t bidx = ((size_t)r * 128 + kh * 64 + oo * 8) >> 3;
        bool av = (row0 + r) < n;
        uint4 va, vb;
        if (Af) {
            float4 f0 = make_float4(0.f, 0.f, 0.f, 0.f), f1 = f0;
            if (av) {
                f0 = *reinterpret_cast<const float4*>(&Af[elem]);
                f1 = *reinterpret_cast<const float4*>(&Af[elem + 4]);
            }
            __nv_bfloat162 h0 = __floats2bfloat162_rn(f0.x, f0.y);
            __nv_bfloat162 h1 = __floats2bfloat162_rn(f0.z, f0.w);
            __nv_bfloat162 h2 = __floats2bfloat162_rn(f1.x, f1.y);
            __nv_bfloat162 h3 = __floats2bfloat162_rn(f1.z, f1.w);
            __nv_bfloat162 l0 = __floats2bfloat162_rn(f0.x - __bfloat162float(h0.x), f0.y - __bfloat162float(h0.y));
            __nv_bfloat162 l1 = __floats2bfloat162_rn(f0.z - __bfloat162float(h1.x), f0.w - __bfloat162float(h1.y));
            __nv_bfloat162 l2 = __floats2bfloat162_rn(f1.x - __bfloat162float(h2.x), f1.y - __bfloat162float(h2.y));
            __nv_bfloat162 l3 = __floats2bfloat162_rn(f1.z - __bfloat162float(h3.x), f1.w - __bfloat162float(h3.y));
            va = make_uint4(*(uint32_t*)&h0, *(uint32_t*)&h1, *(uint32_t*)&h2, *(uint32_t*)&h3);
            vb = make_uint4(*(uint32_t*)&l0, *(uint32_t*)&l1, *(uint32_t*)&l2, *(uint32_t*)&l3);
        } else {
            va = av ? reinterpret_cast<const uint4*>(Ahi)[elem >> 3] : zero4;
            vb = av ? reinterpret_cast<const uint4*>(Alo)[elem >> 3] : zero4;
        }
        uint4 wh = reinterpret_cast<const uint4*>(Bhi)[bidx];
        uint4 wl = reinterpret_cast<const uint4*>(Blo)[bidx];
        *reinterpret_cast<uint4*>(smem + (sAhi - sb) + soff) = va;
        *reinterpret_cast<uint4*>(smem + (sAlo - sb) + soff) = vb;
        *reinterpret_cast<uint4*>(smem + (sBhi - sb) + soff) = wh;
        *reinterpret_cast<uint4*>(smem + (sBlo - sb) + soff) = wl;
    }
    __syncthreads();

#pragma unroll
    for (int kh = 0; kh < 2; kh++) {
        uint32_t hoff = (uint32_t)(kh * 16384);
#pragma unroll
        for (int kk = 0; kk < 4; kk++) {
            int lr = lane & 15;
            int kin = kk * 16 + ((lane >> 4) << 3);
            uint32_t ahi[2][4], alo[2][4], bxh[2][4], bxl[2][4];
#pragma unroll
            for (int mf = 0; mf < 2; mf++) {
                uint32_t off = hoff + SW128((uint32_t)((wm * 32 + mf * 16 + lr) * 128 + kin * 2));
                LDSM4(ahi[mf][0], ahi[mf][1], ahi[mf][2], ahi[mf][3], sAhi + off);
                LDSM4(alo[mf][0], alo[mf][1], alo[mf][2], alo[mf][3], sAlo + off);
            }
#pragma unroll
            for (int nf = 0; nf < 2; nf++) {
                uint32_t off = hoff + SW128((uint32_t)((wn * 32 + nf * 16 + lr) * 128 + kin * 2));
                LDSM4(bxh[nf][0], bxh[nf][1], bxh[nf][2], bxh[nf][3], sBhi + off);
                LDSM4(bxl[nf][0], bxl[nf][1], bxl[nf][2], bxl[nf][3], sBlo + off);
            }
#pragma unroll
            for (int mf = 0; mf < 2; mf++) {
#pragma unroll
                for (int ns = 0; ns < 4; ns++) {
                    int g = ns >> 1, od = ns & 1;
                    uint32_t bh[2] = { bxh[g][od], bxh[g][od + 2] };
                    uint32_t bl[2] = { bxl[g][od], bxl[g][od + 2] };
                    mma16816(acc[mf][ns], ahi[mf], bh);
                    mma16816(acc[mf][ns], ahi[mf], bl);
                    mma16816(acc[mf][ns], alo[mf], bh);
                }
            }
        }
    }

    // ---- epilogue ----
    int qrow = lane >> 2, qcol = (lane & 3) * 2;
#pragma unroll
    for (int mf = 0; mf < 2; mf++) {
#pragma unroll
        for (int ns = 0; ns < 4; ns++) {
            int r0 = row0 + wm * 32 + mf * 16 + qrow;
            int c0 = wn * 32 + ns * 8 + qcol;
            if (r0 < n)
                *reinterpret_cast<float2*>(&C[(size_t)r0 * 128 + c0]) =
                    make_float2(acc[mf][ns][0], acc[mf][ns][1]);
            if (r0 + 8 < n)
                *reinterpret_cast<float2*>(&C[(size_t)(r0 + 8) * 128 + c0]) =
                    make_float2(acc[mf][ns][2], acc[mf][ns][3]);
        }
    }
}

// ---------------- warp helpers ----------------
__device__ __forceinline__ float warp_sum(float v) {
#pragma unroll
    for (int o = 16; o; o >>= 1) v += __shfl_xor_sync(0xffffffffu, v, o);
    return v;
}

// ---------------- per-node alpha (float4-per-lane layout) ----------------
__global__ void k_alpha(const float* __restrict__ h,
                        const float* __restrict__ a_src,
                        const float* __restrict__ a_dst, int n)
{
    int gw = (blockIdx.x * blockDim.x + threadIdx.x) >> 5;
    int lane = threadIdx.x & 31;
    if (gw >= n) return;
    float4 hv = *reinterpret_cast<const float4*>(&h[(size_t)gw * 128 + 4 * lane]);
    float4 as = *reinterpret_cast<const float4*>(&a_src[4 * lane]);
    float4 ad = *reinterpret_cast<const float4*>(&a_dst[4 * lane]);
    float ps = hv.x * as.x + hv.y * as.y + hv.z * as.z + hv.w * as.w;
    float pd = hv.x * ad.x + hv.y * ad.y + hv.z * ad.z + hv.w * ad.w;
    // reduce within 8-lane groups (one head per group)
#pragma unroll
    for (int o = 4; o; o >>= 1) {
        ps += __shfl_xor_sync(0xffffffffu, ps, o);
        pd += __shfl_xor_sync(0xffffffffu, pd, o);
    }
    float s0 = __shfl_sync(0xffffffffu, ps, 0);
    float s1 = __shfl_sync(0xffffffffu, ps, 8);
    float s2 = __shfl_sync(0xffffffffu, ps, 16);
    float s3 = __shfl_sync(0xffffffffu, ps, 24);
    float d0 = __shfl_sync(0xffffffffu, pd, 0);
    float d1 = __shfl_sync(0xffffffffu, pd, 8);
    float d2 = __shfl_sync(0xffffffffu, pd, 16);
    float d3 = __shfl_sync(0xffffffffu, pd, 24);
    if (lane == 0) {
        g_asrc[gw] = make_float4(s0, s1, s2, s3);
        g_adst[gw] = make_float4(d0, d1, d2, d3);
    }
}

// ---------------- fused GAT aggregation + ELU + residual + bf16 split -------
__device__ __forceinline__ float lrelu(float x) { return x >= 0.f ? x : 0.2f * x; }
__device__ __forceinline__ float elu(float x)  { return x > 0.f ? x : expm1f(x); }

// unsafe softmax: p = exp(e) (e clamped at 75), a = p/(sum p + 1e-10).
// reference clamps m=max(seg_max,0): if m==0 identical; if m>0 sum>=1 so the
// 1e-10 epsilon shift is <=1e-10 relative. 2 passes instead of 3.
__global__ void k_edgeagg(const float* __restrict__ h,
                          const float* __restrict__ xprev,
                          float* __restrict__ xnext,
                          __nv_bfloat16* __restrict__ hi,
                          __nv_bfloat16* __restrict__ lo, int n)
{
    __shared__ int   sidx[8][32];
    __shared__ float4 swt[8][32];

    int w = threadIdx.x >> 5;
    int gw = (blockIdx.x * blockDim.x + threadIdx.x) >> 5;
    int lane = threadIdx.x & 31;
    if (gw >= n) return;

    int base = g_rowptr[gw];
    int deg  = g_rowptr[gw + 1] - base;
    float4 ad = g_adst[gw];

    // pass 1: p = exp(e); store; accumulate sums
    float s0 = 0.f, s1 = 0.f, s2 = 0.f, s3 = 0.f;
    for (int i = lane; i < deg; i += 32) {
        int s = g_col[base + i];
        float4 as = g_asrc[s];
        float p0 = expf(fminf(lrelu(as.x + ad.x), 75.f));
        float p1 = expf(fminf(lrelu(as.y + ad.y), 75.f));
        float p2 = expf(fminf(lrelu(as.z + ad.z), 75.f));
        float p3 = expf(fminf(lrelu(as.w + ad.w), 75.f));
        g_ew[base + i] = make_float4(p0, p1, p2, p3);
        s0 += p0; s1 += p1; s2 += p2; s3 += p3;
    }
    s0 = warp_sum(s0); s1 = warp_sum(s1); s2 = warp_sum(s2); s3 = warp_sum(s3);
    float i0 = 1.f / (s0 + 1e-10f);
    float i1 = 1.f / (s1 + 1e-10f);
    float i2 = 1.f / (s2 + 1e-10f);
    float i3 = 1.f / (s3 + 1e-10f);

    // pass 2: aggregation. lane owns dims [4*lane, 4*lane+3] (head lane>>3).
    float4 acc = make_float4(0.f, 0.f, 0.f, 0.f);
    int hsel = lane >> 3;
    for (int bi = 0; bi < deg; bi += 32) {
        int cnt = min(32, deg - bi);
        if (lane < cnt) {
            sidx[w][lane] = g_col[base + bi + lane];
            float4 p = g_ew[base + bi + lane];
            swt[w][lane] = make_float4(p.x * i0, p.y * i1, p.z * i2, p.w * i3);
        }
        __syncwarp();
        for (int j = 0; j < cnt; j++) {
            int s = sidx[w][j];
            float wj = reinterpret_cast<const float*>(&swt[w][j])[hsel];
            float4 hv = *reinterpret_cast<const float4*>(&h[(size_t)s * 128 + 4 * lane]);
            acc.x += hv.x * wj;
            acc.y += hv.y * wj;
            acc.z += hv.z * wj;
            acc.w += hv.w * wj;
        }
        __syncwarp();
    }

    size_t o = (size_t)gw * 128 + 4 * lane;
    float4 xp = *reinterpret_cast<const float4*>(&xprev[o]);
    float4 v = make_float4(elu(acc.x) + xp.x, elu(acc.y) + xp.y,
                           elu(acc.z) + xp.z, elu(acc.w) + xp.w);
    if (xnext) *reinterpret_cast<float4*>(&xnext[o]) = v;
    if (hi) {
        __nv_bfloat162 h0 = __floats2bfloat162_rn(v.x, v.y);
        __nv_bfloat162 h1 = __floats2bfloat162_rn(v.z, v.w);
        __nv_bfloat162 l0 = __floats2bfloat162_rn(v.x - __bfloat162float(h0.x), v.y - __bfloat162float(h0.y));
        __nv_bfloat162 l1 = __floats2bfloat162_rn(v.z - __bfloat162float(h1.x), v.w - __bfloat162float(h1.y));
        uint2 ph = make_uint2(*(uint32_t*)&h0, *(uint32_t*)&h1);
        uint2 pl = make_uint2(*(uint32_t*)&l0, *(uint32_t*)&l1);
        *reinterpret_cast<uint2*>(&hi[o]) = ph;
        *reinterpret_cast<uint2*>(&lo[o]) = pl;
    }
}

// ---------------- pair epilogue ----------------
__global__ void k_pairs(const int* __restrict__ lsrc, const int* __restrict__ ldst,
                        const float* __restrict__ b1, const float* __restrict__ w2,
                        const float* __restrict__ b2, float* __restrict__ out, int p)
{
    int gw = (blockIdx.x * blockDim.x + threadIdx.x) >> 5;
    int lane = threadIdx.x & 31;
    if (gw >= p) return;
    int k = 4 * lane;
    float4 u = *reinterpret_cast<const float4*>(&g_u[(size_t)lsrc[gw] * 128 + k]);
    float4 v = *reinterpret_cast<const float4*>(&g_v[(size_t)ldst[gw] * 128 + k]);
    float4 b = *reinterpret_cast<const float4*>(&b1[k]);
    float4 w = *reinterpret_cast<const float4*>(&w2[k]);
    float t = fmaxf(u.x + v.x + b.x, 0.f) * w.x
            + fmaxf(u.y + v.y + b.y, 0.f) * w.y
            + fmaxf(u.z + v.z + b.z, 0.f) * w.z
            + fmaxf(u.w + v.w + b.w, 0.f) * w.w;
    t = warp_sum(t);
    if (lane == 0) out[gw] = t + b2[0];
}

// ---------------- driver ----------------
extern "C" void kernel_launch(void* const* d_in, const int* in_sizes, int n_in,
                              void* d_out, int out_size)
{
    const float* embed  = (const float*)d_in[0];
    const float* W1     = (const float*)d_in[1];
    const float* a_src1 = (const float*)d_in[2];
    const float* a_dst1 = (const float*)d_in[3];
    const float* W2     = (const float*)d_in[4];
    const float* a_src2 = (const float*)d_in[5];
    const float* a_dst2 = (const float*)d_in[6];
    const float* lp_w1  = (const float*)d_in[7];
    const float* lp_b1  = (const float*)d_in[8];
    const float* lp_w2  = (const float*)d_in[9];
    const float* lp_b2  = (const float*)d_in[10];
    const int*   eidx   = (const int*)d_in[11];
    const int*   lsrc   = (const int*)d_in[12];
    const int*   ldst   = (const int*)d_in[13];
    float* out = (float*)d_out;

    const int N = in_sizes[0] / DDIM;
    const int E = in_sizes[11] / 2;
    const int P = in_sizes[12];
    const int* esrc = eidx;
    const int* edst = eidx + E;

    float* hbuf; cudaGetSymbolAddress((void**)&hbuf, g_h);
    float* x2;   cudaGetSymbolAddress((void**)&x2,   g_x2);
    float* ub;   cudaGetSymbolAddress((void**)&ub,   g_u);
    float* vb;   cudaGetSymbolAddress((void**)&vb,   g_v);
    __nv_bfloat16* ahi; cudaGetSymbolAddress((void**)&ahi, g_ahi);
    __nv_bfloat16* alo; cudaGetSymbolAddress((void**)&alo, g_alo);
    __nv_bfloat16* wthi; cudaGetSymbolAddress((void**)&wthi, g_wthi);
    __nv_bfloat16* wtlo; cudaGetSymbolAddress((void**)&wtlo, g_wtlo);

    cudaFuncSetAttribute(k_gemm_mma, cudaFuncAttributeMaxDynamicSharedMemorySize, GEMM_SMEM);

    const int T = 256;
    int nbN  = (N + T - 1) / T;
    int nbE  = (E + T - 1) / T;
    int nbS  = (N + 1023) / 1024;
    int nbW  = (N * 32 + T - 1) / T;
    int nbPW = (P * 32 + T - 1) / T;
    int nbG  = (N + 127) / 128;
    const int WSZ = DDIM * DDIM;

    // CSR by dst (shared by both layers)
    k_zero_deg<<<nbN, T>>>(N);
    k_hist<<<nbE, T>>>(edst, E);
    k_scan1<<<nbS, 1024>>>(N);
    k_scan2<<<1, 1024>>>(nbS);
    k_scan3<<<nbS, 1024>>>(N, E);
    k_scatter<<<nbE, T>>>(esrc, edst, E);

    // weight transposes/splits
    k_wsplit<<<32, 256>>>(W1,              wthi + 0 * WSZ, wtlo + 0 * WSZ);
    k_wsplit<<<32, 256>>>(W2,              wthi + 1 * WSZ, wtlo + 1 * WSZ);
    k_wsplit<<<32, 256>>>(lp_w1,           wthi + 2 * WSZ, wtlo + 2 * WSZ);
    k_wsplit<<<32, 256>>>(lp_w1 + 128*128, wthi + 3 * WSZ, wtlo + 3 * WSZ);

    // layer 1 (GEMM consumes fp32 embed directly, splitting in-kernel)
    k_gemm_mma<<<nbG, 512, GEMM_SMEM>>>(embed, nullptr, nullptr,
                                        wthi + 0 * WSZ, wtlo + 0 * WSZ, hbuf, N);
    k_alpha<<<nbW, T>>>(hbuf, a_src1, a_dst1, N);
    k_edgeagg<<<nbW, T>>>(hbuf, embed, x2, ahi, alo, N);   // x2 + bf16 split

    // layer 2
    k_gemm_mma<<<nbG, 512, GEMM_SMEM>>>(nullptr, ahi, alo,
                                        wthi + 1 * WSZ, wtlo + 1 * WSZ, hbuf, N);
    k_alpha<<<nbW, T>>>(hbuf, a_src2, a_dst2, N);
    k_edgeagg<<<nbW, T>>>(hbuf, x2, nullptr, ahi, alo, N); // z as bf16 split only

    // link predictor: u = z @ lp_w1[:128], v = z @ lp_w1[128:]
    k_gemm_mma<<<nbG, 512, GEMM_SMEM>>>(nullptr, ahi, alo,
                                        wthi + 2 * WSZ, wtlo + 2 * WSZ, ub, N);
    k_gemm_mma<<<nbG, 512, GEMM_SMEM>>>(nullptr, ahi, alo,
                                        wthi + 3 * WSZ, wtlo + 3 * WSZ, vb, N);
    k_pairs<<<nbPW, T>>>(lsrc, ldst, lp_b1, lp_w2, lp_b2, out, P);
}

// round 7
// speedup vs baseline: 2.6240x; 1.0361x over previous
#include <cuda_runtime.h>
#include <cuda_bf16.h>
#include <math.h>
#include <stdint.h>

#define NMAX 100000
#define EMAX 1600000
#define DDIM 128

// ---------------- scratch (static __device__ arrays; no allocation) ----------
__device__ float g_h [NMAX * DDIM];
__device__ float g_x2[NMAX * DDIM];
__device__ float g_u [NMAX * DDIM];
__device__ float g_v [NMAX * DDIM];
__device__ __nv_bfloat16 g_ahi[NMAX * DDIM];
__device__ __nv_bfloat16 g_alo[NMAX * DDIM];
__device__ __nv_bfloat16 g_wthi[4 * DDIM * DDIM];
__device__ __nv_bfloat16 g_wtlo[4 * DDIM * DDIM];
__device__ float4 g_asrc[NMAX];
__device__ float4 g_adst[NMAX];
__device__ float4 g_ew  [EMAX];      // per-edge unnormalized softmax p=exp(e)
__device__ int g_deg   [NMAX];
__device__ int g_rowptr[NMAX + 1];
__device__ int g_cursor[NMAX];
__device__ int g_col   [EMAX];
__device__ int g_bsums [1024];

__device__ __forceinline__ uint32_t smem_to_u32(const void* p) {
    uint32_t a;
    asm("{ .reg .u64 t; cvta.to.shared.u64 t, %1; cvt.u32.u64 %0, t; }" : "=r"(a) : "l"(p));
    return a;
}
#define SW128(off) ((off) ^ (((off) >> 3) & 0x70))

#define LDSM4(r0, r1, r2, r3, addr) \
    asm volatile("ldmatrix.sync.aligned.m8n8.x4.shared.b16 {%0,%1,%2,%3}, [%4];" \
        : "=r"(r0), "=r"(r1), "=r"(r2), "=r"(r3) : "r"(addr))

__device__ __forceinline__ void mma16816(float* d, const uint32_t* a, const uint32_t* b) {
    asm volatile(
        "mma.sync.aligned.m16n8k16.row.col.f32.bf16.bf16.f32 "
        "{%0,%1,%2,%3},{%4,%5,%6,%7},{%8,%9},{%0,%1,%2,%3};"
        : "+f"(d[0]), "+f"(d[1]), "+f"(d[2]), "+f"(d[3])
        : "r"(a[0]), "r"(a[1]), "r"(a[2]), "r"(a[3]), "r"(b[0]), "r"(b[1]));
}

// ---------------- setup: zero degrees + all 4 weight splits ----------------
__device__ __forceinline__ void wsplit_one(const float* __restrict__ W,
                                           __nv_bfloat16* __restrict__ hi,
                                           __nv_bfloat16* __restrict__ lo, int i) {
    int nn = i >> 6;
    int kp = (i & 63) * 2;
    float x0 = W[(size_t)kp * 128 + nn];
    float x1 = W[(size_t)(kp + 1) * 128 + nn];
    __nv_bfloat162 h = __floats2bfloat162_rn(x0, x1);
    float r0 = x0 - __bfloat162float(h.x);
    float r1 = x1 - __bfloat162float(h.y);
    __nv_bfloat162 l = __floats2bfloat162_rn(r0, r1);
    reinterpret_cast<__nv_bfloat162*>(hi)[i] = h;
    reinterpret_cast<__nv_bfloat162*>(lo)[i] = l;
}

__global__ void k_setup(const float* __restrict__ W1, const float* __restrict__ W2,
                        const float* __restrict__ lpw1,
                        __nv_bfloat16* __restrict__ wthi, __nv_bfloat16* __restrict__ wtlo,
                        int n) {
    const int WSZ = DDIM * DDIM;
    int i = blockIdx.x * blockDim.x + threadIdx.x;
    if (i < n) g_deg[i] = 0;
    if (i < 8192)       wsplit_one(W1,                wthi + 0 * WSZ, wtlo + 0 * WSZ, i);
    else if (i < 16384) wsplit_one(W2,                wthi + 1 * WSZ, wtlo + 1 * WSZ, i - 8192);
    else if (i < 24576) wsplit_one(lpw1,              wthi + 2 * WSZ, wtlo + 2 * WSZ, i - 16384);
    else if (i < 32768) wsplit_one(lpw1 + 128 * 128,  wthi + 3 * WSZ, wtlo + 3 * WSZ, i - 24576);
}

// ---------------- CSR build ----------------
__global__ void k_hist(const int* __restrict__ dst, int e) {
    int i = blockIdx.x * blockDim.x + threadIdx.x;
    if (i < e) atomicAdd(&g_deg[dst[i]], 1);
}
__global__ void k_scan1(int n) {
    __shared__ int sm[1024];
    int tid = threadIdx.x;
    int i = blockIdx.x * 1024 + tid;
    int v = (i < n) ? g_deg[i] : 0;
    sm[tid] = v;
    __syncthreads();
    for (int off = 1; off < 1024; off <<= 1) {
        int t = (tid >= off) ? sm[tid - off] : 0;
        __syncthreads();
        sm[tid] += t;
        __syncthreads();
    }
    if (i < n) g_rowptr[i] = sm[tid] - v;
    if (tid == 1023) g_bsums[blockIdx.x] = sm[1023];
}
__global__ void k_scan2(int nb) {       // nb <= 128
    __shared__ int wsum[4];
    int tid = threadIdx.x;              // 128 threads
    int lane = tid & 31, w = tid >> 5;
    int v = (tid < nb) ? g_bsums[tid] : 0;
    int x = v;
#pragma unroll
    for (int o = 1; o < 32; o <<= 1) {
        int t = __shfl_up_sync(0xffffffffu, x, o);
        if (lane >= o) x += t;
    }
    if (lane == 31) wsum[w] = x;
    __syncthreads();
    int add = 0;
#pragma unroll
    for (int j = 0; j < 4; j++) add += (j < w) ? wsum[j] : 0;
    if (tid < nb) g_bsums[tid] = x - v + add;   // exclusive
}
__global__ void k_scan3(int n, int e) {
    int i = blockIdx.x * 1024 + threadIdx.x;
    if (i < n) {
        int v = g_rowptr[i] + g_bsums[blockIdx.x];
        g_rowptr[i] = v;
        g_cursor[i] = v;
    }
    if (i == 0) g_rowptr[n] = e;
}
__global__ void k_scatter(const int* __restrict__ src, const int* __restrict__ dst, int e) {
    int i = blockIdx.x * blockDim.x + threadIdx.x;
    if (i < e) {
        int d = dst[i];
        int slot = atomicAdd(&g_cursor[d], 1);
        g_col[slot] = src[i];
    }
}

// ---------------- HMMA GEMM + fused alpha ----------------
// C[n,128] = A[n,128] @ W[128,128]; optionally alpha dots in epilogue.
// Full-K resident: 4 bf16 tiles of 32KB = 128KB dynamic smem.
#define GEMM_SMEM 131072

__global__ void __launch_bounds__(512, 1) k_gemm_mma(
    const float* __restrict__ Af,
    const __nv_bfloat16* __restrict__ Ahi, const __nv_bfloat16* __restrict__ Alo,
    const __nv_bfloat16* __restrict__ Bhi, const __nv_bfloat16* __restrict__ Blo,
    float* __restrict__ C,
    const float* __restrict__ a_src, const float* __restrict__ a_dst, int n)
{
    extern __shared__ char smem[];
    __shared__ float sAl[128][4];
    __shared__ float sDl[128][4];
    uint32_t sb = smem_to_u32(smem);
    const uint32_t sAhi = sb;
    const uint32_t sAlo = sb + 32768;
    const uint32_t sBhi = sb + 65536;
    const uint32_t sBlo = sb + 98304;

    int tid = threadIdx.x;
    int wid = tid >> 5, lane = tid & 31;
    int wm = wid & 3, wn = wid >> 2;
    int row0 = blockIdx.x * 128;

    if (a_src && tid < 128) {
        *reinterpret_cast<float4*>(&sAl[tid][0]) = make_float4(0.f, 0.f, 0.f, 0.f);
        *reinterpret_cast<float4*>(&sDl[tid][0]) = make_float4(0.f, 0.f, 0.f, 0.f);
    }

    float acc[2][4][4];
#pragma unroll
    for (int i = 0; i < 2; i++)
#pragma unroll
        for (int j = 0; j < 4; j++)
#pragma unroll
            for (int q = 0; q < 4; q++) acc[i][j][q] = 0.f;

    const uint4 zero4 = make_uint4(0, 0, 0, 0);

#pragma unroll
    for (int t = 0; t < 4; t++) {
        int i = tid + t * 512;
        int r = i >> 4;
        int o = i & 15;
        int kh = o >> 3, oo = o & 7;
        uint32_t soff = (uint32_t)(kh * 16384) + SW128((uint32_t)(r * 128 + oo * 16));
        size_t elem = (size_t)(row0 + r) * 128 + kh * 64 + oo * 8;
        size_t bidx = ((size_t)r * 128 + kh * 64 + oo * 8) >> 3;
        bool av = (row0 + r) < n;
        uint4 va, vb;
        if (Af) {
            float4 f0 = make_float4(0.f, 0.f, 0.f, 0.f), f1 = f0;
            if (av) {
                f0 = *reinterpret_cast<const float4*>(&Af[elem]);
                f1 = *reinterpret_cast<const float4*>(&Af[elem + 4]);
            }
            __nv_bfloat162 h0 = __floats2bfloat162_rn(f0.x, f0.y);
            __nv_bfloat162 h1 = __floats2bfloat162_rn(f0.z, f0.w);
            __nv_bfloat162 h2 = __floats2bfloat162_rn(f1.x, f1.y);
            __nv_bfloat162 h3 = __floats2bfloat162_rn(f1.z, f1.w);
            __nv_bfloat162 l0 = __floats2bfloat162_rn(f0.x - __bfloat162float(h0.x), f0.y - __bfloat162float(h0.y));
            __nv_bfloat162 l1 = __floats2bfloat162_rn(f0.z - __bfloat162float(h1.x), f0.w - __bfloat162float(h1.y));
            __nv_bfloat162 l2 = __floats2bfloat162_rn(f1.x - __bfloat162float(h2.x), f1.y - __bfloat162float(h2.y));
            __nv_bfloat162 l3 = __floats2bfloat162_rn(f1.z - __bfloat162float(h3.x), f1.w - __bfloat162float(h3.y));
            va = make_uint4(*(uint32_t*)&h0, *(uint32_t*)&h1, *(uint32_t*)&h2, *(uint32_t*)&h3);
            vb = make_uint4(*(uint32_t*)&l0, *(uint32_t*)&l1, *(uint32_t*)&l2, *(uint32_t*)&l3);
        } else {
            va = av ? reinterpret_cast<const uint4*>(Ahi)[elem >> 3] : zero4;
            vb = av ? reinterpret_cast<const uint4*>(Alo)[elem >> 3] : zero4;
        }
        uint4 wh = reinterpret_cast<const uint4*>(Bhi)[bidx];
        uint4 wl = reinterpret_cast<const uint4*>(Blo)[bidx];
        *reinterpret_cast<uint4*>(smem + (sAhi - sb) + soff) = va;
        *reinterpret_cast<uint4*>(smem + (sAlo - sb) + soff) = vb;
        *reinterpret_cast<uint4*>(smem + (sBhi - sb) + soff) = wh;
        *reinterpret_cast<uint4*>(smem + (sBlo - sb) + soff) = wl;
    }
    __syncthreads();

#pragma unroll
    for (int kh = 0; kh < 2; kh++) {
        uint32_t hoff = (uint32_t)(kh * 16384);
#pragma unroll
        for (int kk = 0; kk < 4; kk++) {
            int lr = lane & 15;
            int kin = kk * 16 + ((lane >> 4) << 3);
            uint32_t ahi[2][4], alo[2][4], bxh[2][4], bxl[2][4];
#pragma unroll
            for (int mf = 0; mf < 2; mf++) {
                uint32_t off = hoff + SW128((uint32_t)((wm * 32 + mf * 16 + lr) * 128 + kin * 2));
                LDSM4(ahi[mf][0], ahi[mf][1], ahi[mf][2], ahi[mf][3], sAhi + off);
                LDSM4(alo[mf][0], alo[mf][1], alo[mf][2], alo[mf][3], sAlo + off);
            }
#pragma unroll
            for (int nf = 0; nf < 2; nf++) {
                uint32_t off = hoff + SW128((uint32_t)((wn * 32 + nf * 16 + lr) * 128 + kin * 2));
                LDSM4(bxh[nf][0], bxh[nf][1], bxh[nf][2], bxh[nf][3], sBhi + off);
                LDSM4(bxl[nf][0], bxl[nf][1], bxl[nf][2], bxl[nf][3], sBlo + off);
            }
#pragma unroll
            for (int mf = 0; mf < 2; mf++) {
#pragma unroll
                for (int ns = 0; ns < 4; ns++) {
                    int g = ns >> 1, od = ns & 1;
                    uint32_t bh[2] = { bxh[g][od], bxh[g][od + 2] };
                    uint32_t bl[2] = { bxl[g][od], bxl[g][od + 2] };
                    mma16816(acc[mf][ns], ahi[mf], bh);
                    mma16816(acc[mf][ns], ahi[mf], bl);
                    mma16816(acc[mf][ns], alo[mf], bh);
                }
            }
        }
    }

    // ---- epilogue ----
    int qrow = lane >> 2, qcol = (lane & 3) * 2;

    if (a_src) {
        float2 s2[4], d2[4];
#pragma unroll
        for (int ns = 0; ns < 4; ns++) {
            int c = wn * 32 + ns * 8 + qcol;
            s2[ns] = *reinterpret_cast<const float2*>(&a_src[c]);
            d2[ns] = *reinterpret_cast<const float2*>(&a_dst[c]);
        }
#pragma unroll
        for (int mf = 0; mf < 2; mf++) {
            int rl = wm * 32 + mf * 16 + qrow;
            float pa0 = 0.f, pd0 = 0.f, pa1 = 0.f, pd1 = 0.f;
#pragma unroll
            for (int ns = 0; ns < 4; ns++) {
                pa0 += acc[mf][ns][0] * s2[ns].x + acc[mf][ns][1] * s2[ns].y;
                pd0 += acc[mf][ns][0] * d2[ns].x + acc[mf][ns][1] * d2[ns].y;
                pa1 += acc[mf][ns][2] * s2[ns].x + acc[mf][ns][3] * s2[ns].y;
                pd1 += acc[mf][ns][2] * d2[ns].x + acc[mf][ns][3] * d2[ns].y;
            }
            atomicAdd(&sAl[rl][wn], pa0);     atomicAdd(&sDl[rl][wn], pd0);
            atomicAdd(&sAl[rl + 8][wn], pa1); atomicAdd(&sDl[rl + 8][wn], pd1);
        }
    }

#pragma unroll
    for (int mf = 0; mf < 2; mf++) {
#pragma unroll
        for (int ns = 0; ns < 4; ns++) {
            int r0 = row0 + wm * 32 + mf * 16 + qrow;
            int c0 = wn * 32 + ns * 8 + qcol;
            if (r0 < n)
                *reinterpret_cast<float2*>(&C[(size_t)r0 * 128 + c0]) =
                    make_float2(acc[mf][ns][0], acc[mf][ns][1]);
            if (r0 + 8 < n)
                *reinterpret_cast<float2*>(&C[(size_t)(r0 + 8) * 128 + c0]) =
                    make_float2(acc[mf][ns][2], acc[mf][ns][3]);
        }
    }

    if (a_src) {
        __syncthreads();
        if (tid < 128 && row0 + tid < n) {
            g_asrc[row0 + tid] = *reinterpret_cast<float4*>(&sAl[tid][0]);
            g_adst[row0 + tid] = *reinterpret_cast<float4*>(&sDl[tid][0]);
        }
    }
}

// ---------------- dual-B HMMA GEMM: C1 = A@W3, C2 = A@W4 (A loaded once) ----
#define GEMM2_SMEM 196608

__global__ void __launch_bounds__(512, 1) k_gemm_mma2(
    const __nv_bfloat16* __restrict__ Ahi, const __nv_bfloat16* __restrict__ Alo,
    const __nv_bfloat16* __restrict__ B1hi, const __nv_bfloat16* __restrict__ B1lo,
    const __nv_bfloat16* __restrict__ B2hi, const __nv_bfloat16* __restrict__ B2lo,
    float* __restrict__ C1, float* __restrict__ C2, int n)
{
    extern __shared__ char smem[];
    uint32_t sb = smem_to_u32(smem);
    const uint32_t sAhi = sb;
    const uint32_t sAlo = sb + 32768;

    int tid = threadIdx.x;
    int wid = tid >> 5, lane = tid & 31;
    int wm = wid & 3, wn = wid >> 2;
    int row0 = blockIdx.x * 128;

    const uint4 zero4 = make_uint4(0, 0, 0, 0);

    // fill A + both B pairs (6 tiles x 2048 uint4 / 512 thr = 4 iters x 6 stores)
#pragma unroll
    for (int t = 0; t < 4; t++) {
        int i = tid + t * 512;
        int r = i >> 4;
        int o = i & 15;
        int kh = o >> 3, oo = o & 7;
        uint32_t soff = (uint32_t)(kh * 16384) + SW128((uint32_t)(r * 128 + oo * 16));
        size_t elem = (size_t)(row0 + r) * 128 + kh * 64 + oo * 8;
        size_t bidx = ((size_t)r * 128 + kh * 64 + oo * 8) >> 3;
        bool av = (row0 + r) < n;
        uint4 va = av ? reinterpret_cast<const uint4*>(Ahi)[elem >> 3] : zero4;
        uint4 vb = av ? reinterpret_cast<const uint4*>(Alo)[elem >> 3] : zero4;
        *reinterpret_cast<uint4*>(smem + 0      + soff) = va;
        *reinterpret_cast<uint4*>(smem + 32768  + soff) = vb;
        *reinterpret_cast<uint4*>(smem + 65536  + soff) = reinterpret_cast<const uint4*>(B1hi)[bidx];
        *reinterpret_cast<uint4*>(smem + 98304  + soff) = reinterpret_cast<const uint4*>(B1lo)[bidx];
        *reinterpret_cast<uint4*>(smem + 131072 + soff) = reinterpret_cast<const uint4*>(B2hi)[bidx];
        *reinterpret_cast<uint4*>(smem + 163840 + soff) = reinterpret_cast<const uint4*>(B2lo)[bidx];
    }
    __syncthreads();

    for (int g = 0; g < 2; g++) {
        uint32_t sBhi = sb + 65536 + (uint32_t)g * 65536;
        uint32_t sBlo = sBhi + 32768;
        float* C = g ? C2 : C1;

        float acc[2][4][4];
#pragma unroll
        for (int i = 0; i < 2; i++)
#pragma unroll
            for (int j = 0; j < 4; j++)
#pragma unroll
                for (int q = 0; q < 4; q++) acc[i][j][q] = 0.f;

#pragma unroll
        for (int kh = 0; kh < 2; kh++) {
            uint32_t hoff = (uint32_t)(kh * 16384);
#pragma unroll
            for (int kk = 0; kk < 4; kk++) {
                int lr = lane & 15;
                int kin = kk * 16 + ((lane >> 4) << 3);
                uint32_t ahi[2][4], alo[2][4], bxh[2][4], bxl[2][4];
#pragma unroll
                for (int mf = 0; mf < 2; mf++) {
                    uint32_t off = hoff + SW128((uint32_t)((wm * 32 + mf * 16 + lr) * 128 + kin * 2));
                    LDSM4(ahi[mf][0], ahi[mf][1], ahi[mf][2], ahi[mf][3], sAhi + off);
                    LDSM4(alo[mf][0], alo[mf][1], alo[mf][2], alo[mf][3], sAlo + off);
                }
#pragma unroll
                for (int nf = 0; nf < 2; nf++) {
                    uint32_t off = hoff + SW128((uint32_t)((wn * 32 + nf * 16 + lr) * 128 + kin * 2));
                    LDSM4(bxh[nf][0], bxh[nf][1], bxh[nf][2], bxh[nf][3], sBhi + off);
                    LDSM4(bxl[nf][0], bxl[nf][1], bxl[nf][2], bxl[nf][3], sBlo + off);
                }
#pragma unroll
                for (int mf = 0; mf < 2; mf++) {
#pragma unroll
                    for (int ns = 0; ns < 4; ns++) {
                        int gg = ns >> 1, od = ns & 1;
                        uint32_t bh[2] = { bxh[gg][od], bxh[gg][od + 2] };
                        uint32_t bl[2] = { bxl[gg][od], bxl[gg][od + 2] };
                        mma16816(acc[mf][ns], ahi[mf], bh);
                        mma16816(acc[mf][ns], ahi[mf], bl);
                        mma16816(acc[mf][ns], alo[mf], bh);
                    }
                }
            }
        }

        int qrow = lane >> 2, qcol = (lane & 3) * 2;
#pragma unroll
        for (int mf = 0; mf < 2; mf++) {
#pragma unroll
            for (int ns = 0; ns < 4; ns++) {
                int r0 = row0 + wm * 32 + mf * 16 + qrow;
                int c0 = wn * 32 + ns * 8 + qcol;
                if (r0 < n)
                    *reinterpret_cast<float2*>(&C[(size_t)r0 * 128 + c0]) =
                        make_float2(acc[mf][ns][0], acc[mf][ns][1]);
                if (r0 + 8 < n)
                    *reinterpret_cast<float2*>(&C[(size_t)(r0 + 8) * 128 + c0]) =
                        make_float2(acc[mf][ns][2], acc[mf][ns][3]);
            }
        }
    }
}

// ---------------- warp helpers ----------------
__device__ __forceinline__ float warp_sum(float v) {
#pragma unroll
    for (int o = 16; o; o >>= 1) v += __shfl_xor_sync(0xffffffffu, v, o);
    return v;
}

// ---------------- fused GAT aggregation + ELU + residual + bf16 split -------
__device__ __forceinline__ float lrelu(float x) { return x >= 0.f ? x : 0.2f * x; }
__device__ __forceinline__ float elu(float x)  { return x > 0.f ? x : expm1f(x); }

__global__ void k_edgeagg(const float* __restrict__ h,
                          const float* __restrict__ xprev,
                          float* __restrict__ xnext,
                          __nv_bfloat16* __restrict__ hi,
                          __nv_bfloat16* __restrict__ lo, int n)
{
    __shared__ int   sidx[8][32];
    __shared__ float4 swt[8][32];

    int w = threadIdx.x >> 5;
    int gw = (blockIdx.x * blockDim.x + threadIdx.x) >> 5;
    int lane = threadIdx.x & 31;
    if (gw >= n) return;

    int base = g_rowptr[gw];
    int deg  = g_rowptr[gw + 1] - base;
    float4 ad = g_adst[gw];

    float s0 = 0.f, s1 = 0.f, s2 = 0.f, s3 = 0.f;
    for (int i = lane; i < deg; i += 32) {
        int s = g_col[base + i];
        float4 as = g_asrc[s];
        float p0 = expf(fminf(lrelu(as.x + ad.x), 75.f));
        float p1 = expf(fminf(lrelu(as.y + ad.y), 75.f));
        float p2 = expf(fminf(lrelu(as.z + ad.z), 75.f));
        float p3 = expf(fminf(lrelu(as.w + ad.w), 75.f));
        g_ew[base + i] = make_float4(p0, p1, p2, p3);
        s0 += p0; s1 += p1; s2 += p2; s3 += p3;
    }
    s0 = warp_sum(s0); s1 = warp_sum(s1); s2 = warp_sum(s2); s3 = warp_sum(s3);
    float i0 = 1.f / (s0 + 1e-10f);
    float i1 = 1.f / (s1 + 1e-10f);
    float i2 = 1.f / (s2 + 1e-10f);
    float i3 = 1.f / (s3 + 1e-10f);

    float4 acc = make_float4(0.f, 0.f, 0.f, 0.f);
    int hsel = lane >> 3;
    for (int bi = 0; bi < deg; bi += 32) {
        int cnt = min(32, deg - bi);
        if (lane < cnt) {
            sidx[w][lane] = g_col[base + bi + lane];
            float4 p = g_ew[base + bi + lane];
            swt[w][lane] = make_float4(p.x * i0, p.y * i1, p.z * i2, p.w * i3);
        }
        __syncwarp();
        for (int j = 0; j < cnt; j++) {
            int s = sidx[w][j];
            float wj = reinterpret_cast<const float*>(&swt[w][j])[hsel];
            float4 hv = *reinterpret_cast<const float4*>(&h[(size_t)s * 128 + 4 * lane]);
            acc.x += hv.x * wj;
            acc.y += hv.y * wj;
            acc.z += hv.z * wj;
            acc.w += hv.w * wj;
        }
        __syncwarp();
    }

    size_t o = (size_t)gw * 128 + 4 * lane;
    float4 xp = *reinterpret_cast<const float4*>(&xprev[o]);
    float4 v = make_float4(elu(acc.x) + xp.x, elu(acc.y) + xp.y,
                           elu(acc.z) + xp.z, elu(acc.w) + xp.w);
    if (xnext) *reinterpret_cast<float4*>(&xnext[o]) = v;
    if (hi) {
        __nv_bfloat162 h0 = __floats2bfloat162_rn(v.x, v.y);
        __nv_bfloat162 h1 = __floats2bfloat162_rn(v.z, v.w);
        __nv_bfloat162 l0 = __floats2bfloat162_rn(v.x - __bfloat162float(h0.x), v.y - __bfloat162float(h0.y));
        __nv_bfloat162 l1 = __floats2bfloat162_rn(v.z - __bfloat162float(h1.x), v.w - __bfloat162float(h1.y));
        uint2 ph = make_uint2(*(uint32_t*)&h0, *(uint32_t*)&h1);
        uint2 pl = make_uint2(*(uint32_t*)&l0, *(uint32_t*)&l1);
        *reinterpret_cast<uint2*>(&hi[o]) = ph;
        *reinterpret_cast<uint2*>(&lo[o]) = pl;
    }
}

// ---------------- pair epilogue ----------------
__global__ void k_pairs(const int* __restrict__ lsrc, const int* __restrict__ ldst,
                        const float* __restrict__ b1, const float* __restrict__ w2,
                        const float* __restrict__ b2, float* __restrict__ out, int p)
{
    int gw = (blockIdx.x * blockDim.x + threadIdx.x) >> 5;
    int lane = threadIdx.x & 31;
    if (gw >= p) return;
    int k = 4 * lane;
    float4 u = *reinterpret_cast<const float4*>(&g_u[(size_t)lsrc[gw] * 128 + k]);
    float4 v = *reinterpret_cast<const float4*>(&g_v[(size_t)ldst[gw] * 128 + k]);
    float4 b = *reinterpret_cast<const float4*>(&b1[k]);
    float4 w = *reinterpret_cast<const float4*>(&w2[k]);
    float t = fmaxf(u.x + v.x + b.x, 0.f) * w.x
            + fmaxf(u.y + v.y + b.y, 0.f) * w.y
            + fmaxf(u.z + v.z + b.z, 0.f) * w.z
            + fmaxf(u.w + v.w + b.w, 0.f) * w.w;
    t = warp_sum(t);
    if (lane == 0) out[gw] = t + b2[0];
}

// ---------------- driver ----------------
extern "C" void kernel_launch(void* const* d_in, const int* in_sizes, int n_in,
                              void* d_out, int out_size)
{
    const float* embed  = (const float*)d_in[0];
    const float* W1     = (const float*)d_in[1];
    const float* a_src1 = (const float*)d_in[2];
    const float* a_dst1 = (const float*)d_in[3];
    const float* W2     = (const float*)d_in[4];
    const float* a_src2 = (const float*)d_in[5];
    const float* a_dst2 = (const float*)d_in[6];
    const float* lp_w1  = (const float*)d_in[7];
    const float* lp_b1  = (const float*)d_in[8];
    const float* lp_w2  = (const float*)d_in[9];
    const float* lp_b2  = (const float*)d_in[10];
    const int*   eidx   = (const int*)d_in[11];
    const int*   lsrc   = (const int*)d_in[12];
    const int*   ldst   = (const int*)d_in[13];
    float* out = (float*)d_out;

    const int N = in_sizes[0] / DDIM;
    const int E = in_sizes[11] / 2;
    const int P = in_sizes[12];
    const int* esrc = eidx;
    const int* edst = eidx + E;

    float* hbuf; cudaGetSymbolAddress((void**)&hbuf, g_h);
    float* x2;   cudaGetSymbolAddress((void**)&x2,   g_x2);
    float* ub;   cudaGetSymbolAddress((void**)&ub,   g_u);
    float* vb;   cudaGetSymbolAddress((void**)&vb,   g_v);
    __nv_bfloat16* ahi; cudaGetSymbolAddress((void**)&ahi, g_ahi);
    __nv_bfloat16* alo; cudaGetSymbolAddress((void**)&alo, g_alo);
    __nv_bfloat16* wthi; cudaGetSymbolAddress((void**)&wthi, g_wthi);
    __nv_bfloat16* wtlo; cudaGetSymbolAddress((void**)&wtlo, g_wtlo);

    cudaFuncSetAttribute(k_gemm_mma,  cudaFuncAttributeMaxDynamicSharedMemorySize, GEMM_SMEM);
    cudaFuncSetAttribute(k_gemm_mma2, cudaFuncAttributeMaxDynamicSharedMemorySize, GEMM2_SMEM);

    const int T = 256;
    int nbN  = (N + T - 1) / T;
    int nbE  = (E + T - 1) / T;
    int nbS  = (N + 1023) / 1024;
    int nbW  = (N * 32 + T - 1) / T;
    int nbPW = (P * 32 + T - 1) / T;
    int nbG  = (N + 127) / 128;
    const int WSZ = DDIM * DDIM;

    // setup (zero deg + all weight splits), then CSR by dst
    k_setup<<<nbN, T>>>(W1, W2, lp_w1, wthi, wtlo, N);
    k_hist<<<nbE, T>>>(edst, E);
    k_scan1<<<nbS, 1024>>>(N);
    k_scan2<<<1, 128>>>(nbS);
    k_scan3<<<nbS, 1024>>>(N, E);
    k_scatter<<<nbE, T>>>(esrc, edst, E);

    // layer 1 (GEMM splits fp32 embed in-kernel; alpha fused into epilogue)
    k_gemm_mma<<<nbG, 512, GEMM_SMEM>>>(embed, nullptr, nullptr,
                                        wthi + 0 * WSZ, wtlo + 0 * WSZ, hbuf,
                                        a_src1, a_dst1, N);
    k_edgeagg<<<nbW, T>>>(hbuf, embed, x2, ahi, alo, N);

    // layer 2
    k_gemm_mma<<<nbG, 512, GEMM_SMEM>>>(nullptr, ahi, alo,
                                        wthi + 1 * WSZ, wtlo + 1 * WSZ, hbuf,
                                        a_src2, a_dst2, N);
    k_edgeagg<<<nbW, T>>>(hbuf, x2, nullptr, ahi, alo, N);

    // link predictor: u and v in one kernel (A tiles loaded once)
    k_gemm_mma2<<<nbG, 512, GEMM2_SMEM>>>(ahi, alo,
                                          wthi + 2 * WSZ, wtlo + 2 * WSZ,
                                          wthi + 3 * WSZ, wtlo + 3 * WSZ,
                                          ub, vb, N);
    k_pairs<<<nbPW, T>>>(lsrc, ldst, lp_b1, lp_w2, lp_b2, out, P);
}